// round 2
// baseline (speedup 1.0000x reference)
#include <cuda_runtime.h>
#include <math.h>

// Problem constants
#define Bb 128
#define Ss 800
#define Hh 512
#define Ee 256
#define Vv 34
#define Tt 128
#define K1 1280   // ctx(512) + emb(256) + h0(512)
#define K2 1024   // h0(512) + h1(512)
#define KS1 10
#define KS2 8

typedef unsigned long long ull;

// ---------------- persistent device buffers ----------------
__device__ __align__(16) float g_Wp1[K1 * 2048];        // [k][u*4+g]
__device__ __align__(16) float g_Wp2[K2 * 2048];
__device__ __align__(16) float g_Xt1[K1 * Bb];          // [k][b]: 0:512 ctx | 512:768 emb | 768:1280 h0
__device__ __align__(16) float g_Xt2[K2 * Bb];          // 0:512 h0 | 512:1024 h1
__device__ __align__(16) float g_gb1[KS1 * 2048 * Bb];  // split-K partials [ks][j][b]
__device__ __align__(16) float g_gb2[KS2 * 2048 * Bb];
__device__ __align__(16) float g_c0[Hh * Bb];
__device__ __align__(16) float g_c1[Hh * Bb];
__device__ __align__(16) float g_h1v[Hh * Bb];
__device__ __align__(16) float g_tail[Hh * Bb];         // sum_{s>=len} value[b,s,h], [h][b]
__device__ int   g_tok[Bb * Tt];
__device__ int   g_len[Bb];

// ---------------- helpers ----------------
__device__ __forceinline__ float sigf(float x) { return 1.0f / (1.0f + expf(-x)); }

__device__ __forceinline__ ull pk2(float a, float b) {
    ull r; asm("mov.b64 %0,{%1,%2};" : "=l"(r) : "f"(a), "f"(b)); return r;
}
__device__ __forceinline__ ull fma2_(ull a, ull b, ull c) {
    ull d; asm("fma.rn.f32x2 %0,%1,%2,%3;" : "=l"(d) : "l"(a), "l"(b), "l"(c)); return d;
}
__device__ __forceinline__ float2 u2f2(ull v) {
    float2 f; asm("mov.b64 {%0,%1},%2;" : "=f"(f.x), "=f"(f.y) : "l"(v)); return f;
}

// ---------------- setup kernels ----------------
__global__ void k_convert(const void* dec, const void* lens) {
    const int* L = (const int*)lens;
    bool is64 = (L[1] == 0 && L[3] == 0 && L[5] == 0 && L[7] == 0);
    int tid = threadIdx.x;
    for (int i = tid; i < Bb; i += 256)
        g_len[i] = is64 ? (int)((const long long*)lens)[i] : L[i];
    const int* D = (const int*)dec;
    for (int i = tid; i < Bb * Tt; i += 256)
        g_tok[i] = is64 ? (int)((const long long*)dec)[i] : D[i];
}

__global__ void k_pack(const float* __restrict__ Wih1, const float* __restrict__ Whh1,
                       const float* __restrict__ Wih2, const float* __restrict__ Whh2) {
    int stride = gridDim.x * blockDim.x;
    for (int i = blockIdx.x * blockDim.x + threadIdx.x; i < K1 * 2048; i += stride) {
        int k = i >> 11, c = i & 2047;
        int u = c >> 2, g = c & 3;
        int j = g * Hh + u;
        g_Wp1[i] = (k < 768) ? Wih1[j * 768 + k] : Whh1[j * 512 + (k - 768)];
    }
    for (int i = blockIdx.x * blockDim.x + threadIdx.x; i < K2 * 2048; i += stride) {
        int k = i >> 11, c = i & 2047;
        int u = c >> 2, g = c & 3;
        int j = g * Hh + u;
        g_Wp2[i] = (k < 512) ? Wih2[j * 512 + k] : Whh2[j * 512 + (k - 512)];
    }
}

__global__ void k_tail(const float* __restrict__ value) {
    int idx = blockIdx.x * blockDim.x + threadIdx.x;  // 65536
    int h = idx & 511, b = idx >> 9;
    int len = g_len[b];
    float acc = 0.0f;
    const float* vb = value + (size_t)b * Ss * Hh + h;
    for (int s = len; s < Ss; s++) acc += vb[(size_t)s * Hh];
    g_tail[h * Bb + b] = acc;
}

__global__ void k_init(const float* __restrict__ key, const float* __restrict__ emb) {
    int stride = gridDim.x * blockDim.x;
    for (int idx = blockIdx.x * blockDim.x + threadIdx.x; idx < K2 * Bb; idx += stride) {
        g_Xt2[idx] = 0.0f;
        if (idx < Hh * Bb) {
            g_c0[idx] = 0.0f; g_c1[idx] = 0.0f; g_h1v[idx] = 0.0f;
            // ctx init = key[:,0,:]  (Xt1[h][b], idx = h*128+b)
            int b = idx & 127, h = idx >> 7;
            g_Xt1[idx] = key[(size_t)b * Ss * Hh + h];
            g_Xt1[768 * Bb + idx] = 0.0f;  // h0 = 0
        }
        if (idx < Ee * Bb) {
            int b = idx & 127, e = idx >> 7;
            int tok = g_tok[b * Tt + 0];
            g_Xt1[(512 + e) * Bb + b] = emb[tok * Ee + e];
        }
    }
}

// ---------------- LSTM GEMM (split-K, f32x2) ----------------
// grid (32, KSPLIT), block 256.  Block covers 16 u-cols x 4 gates x all 128 b,
// K-chunk of 128 (4 tiles of 32).  Warp w: u = u0 + 2w + {0,1}.
__global__ void __launch_bounds__(256) k_gemm(int which) {
    const float* X  = (which == 1) ? g_Xt1 : g_Xt2;
    const float* Wp = (which == 1) ? g_Wp1 : g_Wp2;
    float* gout     = (which == 1) ? g_gb1 : g_gb2;

    int u0 = blockIdx.x * 16;
    int tid = threadIdx.x, lane = tid & 31, warp = tid >> 5;

    __shared__ __align__(16) float Xs[32 * 128];
    __shared__ __align__(16) ull   Wsd[32 * 64];

    ull acc[8][2];
#pragma unroll
    for (int q = 0; q < 8; q++) { acc[q][0] = 0ull; acc[q][1] = 0ull; }

    for (int kt = 0; kt < 128; kt += 32) {
        int k0 = blockIdx.y * 128 + kt;
        // load X tile [32k][128b]
        const float4* Xg = (const float4*)(X + (size_t)k0 * Bb);
        float4* Xs4 = (float4*)Xs;
#pragma unroll
        for (int r = 0; r < 4; r++) Xs4[tid + 256 * r] = Xg[tid + 256 * r];
        // load W tile duplicated pairs: Wsd[kk][c], c = uu*4+g
#pragma unroll
        for (int r = 0; r < 8; r++) {
            int i = tid + 256 * r;
            int kk = i >> 6, c = i & 63;
            float w = Wp[(size_t)(k0 + kk) * 2048 + u0 * 4 + c];
            Wsd[kk * 64 + c] = pk2(w, w);
        }
        __syncthreads();
#pragma unroll 8
        for (int kk = 0; kk < 32; kk++) {
            const ull* xr = (const ull*)(Xs + kk * 128);
            ull x0 = xr[lane], x1 = xr[32 + lane];
            const ull* wr = Wsd + kk * 64 + warp * 8;
#pragma unroll
            for (int q = 0; q < 8; q++) {
                acc[q][0] = fma2_(x0, wr[q], acc[q][0]);
                acc[q][1] = fma2_(x1, wr[q], acc[q][1]);
            }
        }
        __syncthreads();
    }
    // epilogue: partials -> gout[ks][j][b]
    size_t base = (size_t)blockIdx.y * (2048 * Bb);
#pragma unroll
    for (int q = 0; q < 8; q++) {
        int uu = q >> 2, g = q & 3;
        int j = g * Hh + u0 + warp * 2 + uu;
        float2* row = (float2*)(gout + base + (size_t)j * Bb);
        row[lane]      = u2f2(acc[q][0]);
        row[32 + lane] = u2f2(acc[q][1]);
    }
}

// ---------------- gate (reduce split-K + bias + nonlinearity) ----------------
__global__ void k_gate(int which, const float* __restrict__ bias) {
    int idx = blockIdx.x * blockDim.x + threadIdx.x;  // 65536, = u*128+b
    int b = idx & 127, u = idx >> 7;
    const float* gb = (which == 1) ? g_gb1 : g_gb2;
    int ksp = (which == 1) ? KS1 : KS2;
    float gi = bias[u], gf = bias[512 + u], gg = bias[1024 + u], go = bias[1536 + u];
    for (int ks = 0; ks < ksp; ks++) {
        const float* p = gb + (size_t)ks * (2048 * Bb);
        gi += p[u * Bb + b];
        gf += p[(512 + u) * Bb + b];
        gg += p[(1024 + u) * Bb + b];
        go += p[(1536 + u) * Bb + b];
    }
    float* cb = (which == 1) ? g_c0 : g_c1;
    float c = cb[idx];
    float cn = sigf(gf) * c + sigf(gi) * tanhf(gg);
    float h = sigf(go) * tanhf(cn);
    cb[idx] = cn;
    if (which == 1) { g_Xt1[768 * Bb + idx] = h; g_Xt2[idx] = h; }
    else            { g_Xt2[512 * Bb + idx] = h; g_h1v[idx]  = h; }
}

// ---------------- attention + fc + emb prefill (one block per batch) --------
__global__ void __launch_bounds__(1024) k_attn(
    const float* __restrict__ key, const float* __restrict__ value,
    const float* __restrict__ emb, const float* __restrict__ fcW,
    const float* __restrict__ fcb, float* __restrict__ out, int t)
{
    int b = blockIdx.x;
    int tid = threadIdx.x, lane = tid & 31, warp = tid >> 5;

    __shared__ __align__(16) float sh1[Hh];
    __shared__ __align__(16) float sc[Ss];
    __shared__ __align__(16) float red[32];
    __shared__ __align__(16) float sb[2];
    __shared__ __align__(16) float sctx[8 * Hh];

    if (tid < Hh) sh1[tid] = g_h1v[tid * Bb + b];
    __syncthreads();

    // ---- scores: sc[s] = key[b,s,:] . h1 ----
    const float4* k4 = (const float4*)(key + (size_t)b * Ss * Hh);
    const float4* h14 = (const float4*)sh1;
    for (int s = warp; s < Ss; s += 32) {
        const float4* kr = k4 + (size_t)s * 128;
        float a = 0.0f;
#pragma unroll
        for (int i = 0; i < 4; i++) {
            float4 kv = kr[lane + 32 * i];
            float4 hv = h14[lane + 32 * i];
            a += kv.x * hv.x + kv.y * hv.y + kv.z * hv.z + kv.w * hv.w;
        }
#pragma unroll
        for (int o = 16; o; o >>= 1) a += __shfl_xor_sync(0xffffffffu, a, o);
        if (lane == 0) sc[s] = a;
    }
    __syncthreads();

    // ---- softmax over all 800 (masked included in denominator) ----
    float m = (tid < Ss) ? sc[tid] : -3.4e38f;
#pragma unroll
    for (int o = 16; o; o >>= 1) m = fmaxf(m, __shfl_xor_sync(0xffffffffu, m, o));
    if (lane == 0) red[warp] = m;
    __syncthreads();
    if (warp == 0) {
        float v = red[lane];
#pragma unroll
        for (int o = 16; o; o >>= 1) v = fmaxf(v, __shfl_xor_sync(0xffffffffu, v, o));
        if (lane == 0) sb[0] = v;
    }
    __syncthreads();
    float mx = sb[0];
    float e = 0.0f;
    if (tid < Ss) { e = expf(sc[tid] - mx); sc[tid] = e; }
    float su = e;
#pragma unroll
    for (int o = 16; o; o >>= 1) su += __shfl_xor_sync(0xffffffffu, su, o);
    __syncthreads();
    if (lane == 0) red[warp] = su;
    __syncthreads();
    if (warp == 0) {
        float v = red[lane];
#pragma unroll
        for (int o = 16; o; o >>= 1) v += __shfl_xor_sync(0xffffffffu, v, o);
        if (lane == 0) sb[1] = v;
    }
    __syncthreads();
    float rinv = 1.0f / sb[1];
    int len = g_len[b];

    // ---- ctx = rinv * sum_{s<len} e_s v_s + 1e-9 * tail ----
    int c4 = tid & 127, part = tid >> 7;
    const float4* v4 = (const float4*)(value + (size_t)b * Ss * Hh);
    float4 a4 = make_float4(0.f, 0.f, 0.f, 0.f);
    for (int s = part; s < len; s += 8) {
        float ee = sc[s];
        float4 v = v4[(size_t)s * 128 + c4];
        a4.x += ee * v.x; a4.y += ee * v.y; a4.z += ee * v.z; a4.w += ee * v.w;
    }
    ((float4*)sctx)[part * 128 + c4] = a4;
    __syncthreads();
    if (tid < Hh) {
        float v = 0.0f;
#pragma unroll
        for (int p = 0; p < 8; p++) v += sctx[p * Hh + tid];
        g_Xt1[tid * Bb + b] = v * rinv + 1e-9f * g_tail[tid * Bb + b];
    }

    // ---- fc logits ----
    for (int v = warp; v < Vv; v += 32) {
        const float4* fw = (const float4*)(fcW + v * Hh);
        float a = 0.0f;
#pragma unroll
        for (int i = 0; i < 4; i++) {
            float4 wv = fw[lane + 32 * i];
            float4 hv = h14[lane + 32 * i];
            a += wv.x * hv.x + wv.y * hv.y + wv.z * hv.z + wv.w * hv.w;
        }
#pragma unroll
        for (int o = 16; o; o >>= 1) a += __shfl_xor_sync(0xffffffffu, a, o);
        if (lane == 0) out[(size_t)b * (Tt * Vv) + t * Vv + v] = a + fcb[v];
    }

    // ---- prefill embedding for next step ----
    if (t < Tt - 1 && tid < Ee) {
        int tok = g_tok[b * Tt + (t + 1)];
        g_Xt1[(512 + tid) * Bb + b] = emb[tok * Ee + tid];
    }
}

// ---------------- host ----------------
extern "C" void kernel_launch(void* const* d_in, const int* in_sizes, int n_in,
                              void* d_out, int out_size) {
    const float* key   = (const float*)d_in[0];
    const float* value = (const float*)d_in[1];
    const void*  dec   = d_in[2];
    const void*  lens  = d_in[3];
    const float* emb   = (const float*)d_in[4];
    const float* Wih1  = (const float*)d_in[5];
    const float* Whh1  = (const float*)d_in[6];
    const float* b1    = (const float*)d_in[7];
    const float* Wih2  = (const float*)d_in[8];
    const float* Whh2  = (const float*)d_in[9];
    const float* b2    = (const float*)d_in[10];
    const float* fcW   = (const float*)d_in[11];
    const float* fcb   = (const float*)d_in[12];
    float* out = (float*)d_out;

    k_convert<<<1, 256>>>(dec, lens);
    k_pack<<<2048, 256>>>(Wih1, Whh1, Wih2, Whh2);
    k_tail<<<256, 256>>>(value);
    k_init<<<512, 256>>>(key, emb);

    for (int t = 0; t < Tt; t++) {
        k_gemm<<<dim3(32, KS1), 256>>>(1);
        k_gate<<<64, 1024>>>(1, b1);
        k_gemm<<<dim3(32, KS2), 256>>>(2);
        k_gate<<<64, 1024>>>(2, b2);
        k_attn<<<Bb, 1024>>>(key, value, emb, fcW, fcb, out, t);
    }
}

// round 3
// speedup vs baseline: 1.2143x; 1.2143x over previous
#include <cuda_runtime.h>
#include <cuda_fp16.h>
#include <math.h>

// Problem constants
#define Bb 128
#define Ss 800
#define Hh 512
#define Ee 256
#define Vv 34
#define Tt 128
#define K1 1280   // ctx(512) + emb(256) + h0(512)
#define K2 1024   // h0(512) + h1(512)
#define KS1 10
#define KS2 8
#define KVE (Bb * Ss * Hh)   // 52,428,800 elements

typedef unsigned long long ull;

// ---------------- persistent device buffers ----------------
__device__ __align__(16) __half g_kh[KVE];              // key  fp16 [b][s][h]
__device__ __align__(16) __half g_vh[KVE];              // value fp16 [b][s][h]
__device__ __align__(16) float g_Wp1[K1 * 2048];        // [k][u*4+g]
__device__ __align__(16) float g_Wp2[K2 * 2048];
__device__ __align__(16) float g_Xt1[K1 * Bb];          // [k][b]: 0:512 ctx | 512:768 emb | 768:1280 h0
__device__ __align__(16) float g_Xt2[K2 * Bb];          // 0:512 h0 | 512:1024 h1
__device__ __align__(16) float g_gb1[KS1 * 2048 * Bb];  // split-K partials [ks][j][b]
__device__ __align__(16) float g_gb2[KS2 * 2048 * Bb];
__device__ __align__(16) float g_c0[Hh * Bb];
__device__ __align__(16) float g_c1[Hh * Bb];
__device__ __align__(16) float g_h1v[Hh * Bb];
__device__ __align__(16) float g_tail[Hh * Bb];         // sum_{s>=len} value[b,s,h], [h][b]
__device__ int   g_tok[Bb * Tt];
__device__ int   g_len[Bb];

// ---------------- helpers ----------------
__device__ __forceinline__ float sigf(float x) { return 1.0f / (1.0f + expf(-x)); }

__device__ __forceinline__ ull pk2(float a, float b) {
    ull r; asm("mov.b64 %0,{%1,%2};" : "=l"(r) : "f"(a), "f"(b)); return r;
}
__device__ __forceinline__ ull fma2_(ull a, ull b, ull c) {
    ull d; asm("fma.rn.f32x2 %0,%1,%2,%3;" : "=l"(d) : "l"(a), "l"(b), "l"(c)); return d;
}
__device__ __forceinline__ float2 u2f2(ull v) {
    float2 f; asm("mov.b64 {%0,%1},%2;" : "=f"(f.x), "=f"(f.y) : "l"(v)); return f;
}

// ---------------- setup A: convert tokens/lens + pack weights + fp16 KV -----
__global__ void k_setupA(const void* dec, const void* lens,
                         const float* __restrict__ Wih1, const float* __restrict__ Whh1,
                         const float* __restrict__ Wih2, const float* __restrict__ Whh2,
                         const float* __restrict__ key, const float* __restrict__ value) {
    int gtid = blockIdx.x * blockDim.x + threadIdx.x;
    int stride = gridDim.x * blockDim.x;

    if (blockIdx.x == 0) {
        const int* L = (const int*)lens;
        bool is64 = (L[1] == 0 && L[3] == 0 && L[5] == 0 && L[7] == 0);
        for (int i = threadIdx.x; i < Bb; i += blockDim.x)
            g_len[i] = is64 ? (int)((const long long*)lens)[i] : L[i];
        const int* D = (const int*)dec;
        for (int i = threadIdx.x; i < Bb * Tt; i += blockDim.x)
            g_tok[i] = is64 ? (int)((const long long*)dec)[i] : D[i];
    }

    for (int i = gtid; i < K1 * 2048; i += stride) {
        int k = i >> 11, c = i & 2047;
        int u = c >> 2, g = c & 3;
        int j = g * Hh + u;
        g_Wp1[i] = (k < 768) ? Wih1[j * 768 + k] : Whh1[j * 512 + (k - 768)];
    }
    for (int i = gtid; i < K2 * 2048; i += stride) {
        int k = i >> 11, c = i & 2047;
        int u = c >> 2, g = c & 3;
        int j = g * Hh + u;
        g_Wp2[i] = (k < 512) ? Wih2[j * 512 + k] : Whh2[j * 512 + (k - 512)];
    }

    // fp16 conversions (vectorized: 4 floats -> 4 halves per iter)
    const float4* k4 = (const float4*)key;
    const float4* v4 = (const float4*)value;
    uint2* kh2 = (uint2*)g_kh;
    uint2* vh2 = (uint2*)g_vh;
    for (int i = gtid; i < KVE / 4; i += stride) {
        float4 kf = k4[i];
        half2 lo = __floats2half2_rn(kf.x, kf.y), hi = __floats2half2_rn(kf.z, kf.w);
        uint2 st; st.x = *(unsigned*)&lo; st.y = *(unsigned*)&hi;
        kh2[i] = st;
        float4 vf = v4[i];
        half2 lo2 = __floats2half2_rn(vf.x, vf.y), hi2 = __floats2half2_rn(vf.z, vf.w);
        uint2 sv; sv.x = *(unsigned*)&lo2; sv.y = *(unsigned*)&hi2;
        vh2[i] = sv;
    }
}

// ---------------- setup B: tail sums + state init ---------------------------
__global__ void k_setupB(const float* __restrict__ key, const float* __restrict__ value,
                         const float* __restrict__ emb) {
    int gtid = blockIdx.x * blockDim.x + threadIdx.x;
    int stride = gridDim.x * blockDim.x;

    for (int idx = gtid; idx < K2 * Bb; idx += stride) {
        g_Xt2[idx] = 0.0f;
        if (idx < Hh * Bb) {
            g_c0[idx] = 0.0f; g_c1[idx] = 0.0f; g_h1v[idx] = 0.0f;
            int b = idx & 127, h = idx >> 7;
            g_Xt1[idx] = key[(size_t)b * Ss * Hh + h];   // ctx init = key[:,0,:]
            g_Xt1[768 * Bb + idx] = 0.0f;                // h0 = 0
        }
        if (idx < Ee * Bb) {
            int b = idx & 127, e = idx >> 7;
            int tok = g_tok[b * Tt + 0];
            g_Xt1[(512 + e) * Bb + b] = emb[tok * Ee + e];
        }
    }
    for (int idx = gtid; idx < Hh * Bb; idx += stride) {
        int h = idx & 511, b = idx >> 9;
        int len = g_len[b];
        float acc = 0.0f;
        const float* vb = value + (size_t)b * Ss * Hh + h;
        for (int s = len; s < Ss; s++) acc += vb[(size_t)s * Hh];
        g_tail[h * Bb + b] = acc;
    }
}

// ---------------- LSTM GEMM (split-K, f32x2) ----------------
__global__ void __launch_bounds__(256) k_gemm(int which) {
    const float* X  = (which == 1) ? g_Xt1 : g_Xt2;
    const float* Wp = (which == 1) ? g_Wp1 : g_Wp2;
    float* gout     = (which == 1) ? g_gb1 : g_gb2;

    int u0 = blockIdx.x * 16;
    int tid = threadIdx.x, lane = tid & 31, warp = tid >> 5;

    __shared__ __align__(16) float Xs[32 * 128];
    __shared__ __align__(16) ull   Wsd[32 * 64];

    ull acc[8][2];
#pragma unroll
    for (int q = 0; q < 8; q++) { acc[q][0] = 0ull; acc[q][1] = 0ull; }

    for (int kt = 0; kt < 128; kt += 32) {
        int k0 = blockIdx.y * 128 + kt;
        const float4* Xg = (const float4*)(X + (size_t)k0 * Bb);
        float4* Xs4 = (float4*)Xs;
#pragma unroll
        for (int r = 0; r < 4; r++) Xs4[tid + 256 * r] = Xg[tid + 256 * r];
#pragma unroll
        for (int r = 0; r < 8; r++) {
            int i = tid + 256 * r;
            int kk = i >> 6, c = i & 63;
            float w = Wp[(size_t)(k0 + kk) * 2048 + u0 * 4 + c];
            Wsd[kk * 64 + c] = pk2(w, w);
        }
        __syncthreads();
#pragma unroll 8
        for (int kk = 0; kk < 32; kk++) {
            const ull* xr = (const ull*)(Xs + kk * 128);
            ull x0 = xr[lane], x1 = xr[32 + lane];
            const ull* wr = Wsd + kk * 64 + warp * 8;
#pragma unroll
            for (int q = 0; q < 8; q++) {
                acc[q][0] = fma2_(x0, wr[q], acc[q][0]);
                acc[q][1] = fma2_(x1, wr[q], acc[q][1]);
            }
        }
        __syncthreads();
    }
    size_t base = (size_t)blockIdx.y * (2048 * Bb);
#pragma unroll
    for (int q = 0; q < 8; q++) {
        int uu = q >> 2, g = q & 3;
        int j = g * Hh + u0 + warp * 2 + uu;
        float2* row = (float2*)(gout + base + (size_t)j * Bb);
        row[lane]      = u2f2(acc[q][0]);
        row[32 + lane] = u2f2(acc[q][1]);
    }
}

// ---------------- gate (reduce split-K + bias + nonlinearity) ----------------
__global__ void k_gate(int which, const float* __restrict__ bias) {
    int idx = blockIdx.x * blockDim.x + threadIdx.x;  // 65536, = u*128+b
    int b = idx & 127, u = idx >> 7;
    const float* gb = (which == 1) ? g_gb1 : g_gb2;
    int ksp = (which == 1) ? KS1 : KS2;
    float gi = bias[u], gf = bias[512 + u], gg = bias[1024 + u], go = bias[1536 + u];
    for (int ks = 0; ks < ksp; ks++) {
        const float* p = gb + (size_t)ks * (2048 * Bb);
        gi += p[u * Bb + b];
        gf += p[(512 + u) * Bb + b];
        gg += p[(1024 + u) * Bb + b];
        go += p[(1536 + u) * Bb + b];
    }
    float* cb = (which == 1) ? g_c0 : g_c1;
    float c = cb[idx];
    float cn = sigf(gf) * c + sigf(gi) * tanhf(gg);
    float h = sigf(go) * tanhf(cn);
    cb[idx] = cn;
    if (which == 1) { g_Xt1[768 * Bb + idx] = h; g_Xt2[idx] = h; }
    else            { g_Xt2[512 * Bb + idx] = h; g_h1v[idx]  = h; }
}

// ---------------- attention + fc + emb prefill (one block per batch) --------
__global__ void __launch_bounds__(1024) k_attn(
    const float* __restrict__ emb, const float* __restrict__ fcW,
    const float* __restrict__ fcb, float* __restrict__ out, int t)
{
    int b = blockIdx.x;
    int tid = threadIdx.x, lane = tid & 31, warp = tid >> 5;

    __shared__ __align__(16) float sh1[Hh];       // h1 fp32 (fc pass)
    __shared__ __align__(16) half2 sh1h[Hh / 2];  // h1 fp16 pairs (score pass)
    __shared__ __align__(16) float sc[Ss];
    __shared__ __align__(16) float red[32];
    __shared__ __align__(16) float sb[2];
    __shared__ __align__(16) float sctx[16 * Hh / 8 * 8];  // 16 parts x 512

    if (tid < Hh) sh1[tid] = g_h1v[tid * Bb + b];
    __syncthreads();
    if (tid < Hh / 2) sh1h[tid] = __floats2half2_rn(sh1[2 * tid], sh1[2 * tid + 1]);
    __syncthreads();

    // preload this lane's h1 slice into registers: h = (lane+32i)*8 .. +8
    half2 h1r[2][4];
#pragma unroll
    for (int i = 0; i < 2; i++) {
        const uint4 hv = ((const uint4*)sh1h)[lane + 32 * i];
        h1r[i][0] = *(const half2*)&hv.x; h1r[i][1] = *(const half2*)&hv.y;
        h1r[i][2] = *(const half2*)&hv.z; h1r[i][3] = *(const half2*)&hv.w;
    }

    // ---- scores: sc[s] = key[b,s,:] . h1 ----
    const uint4* k4 = (const uint4*)(g_kh + (size_t)b * Ss * Hh);  // 64 uint4/row
    for (int s = warp; s < Ss; s += 32) {
        const uint4* kr = k4 + (size_t)s * 64;
        float a = 0.0f;
#pragma unroll
        for (int i = 0; i < 2; i++) {
            uint4 kv = kr[lane + 32 * i];
            const half2* kp = (const half2*)&kv;
#pragma unroll
            for (int j = 0; j < 4; j++) {
                float2 kf = __half22float2(kp[j]);
                float2 hf = __half22float2(h1r[i][j]);
                a += kf.x * hf.x + kf.y * hf.y;
            }
        }
#pragma unroll
        for (int o = 16; o; o >>= 1) a += __shfl_xor_sync(0xffffffffu, a, o);
        if (lane == 0) sc[s] = a;
    }
    __syncthreads();

    // ---- softmax over all 800 (masked included in denominator) ----
    float m = (tid < Ss) ? sc[tid] : -3.4e38f;
#pragma unroll
    for (int o = 16; o; o >>= 1) m = fmaxf(m, __shfl_xor_sync(0xffffffffu, m, o));
    if (lane == 0) red[warp] = m;
    __syncthreads();
    if (warp == 0) {
        float v = red[lane];
#pragma unroll
        for (int o = 16; o; o >>= 1) v = fmaxf(v, __shfl_xor_sync(0xffffffffu, v, o));
        if (lane == 0) sb[0] = v;
    }
    __syncthreads();
    float mx = sb[0];
    float e = 0.0f;
    if (tid < Ss) { e = expf(sc[tid] - mx); sc[tid] = e; }
    float su = e;
#pragma unroll
    for (int o = 16; o; o >>= 1) su += __shfl_xor_sync(0xffffffffu, su, o);
    __syncthreads();
    if (lane == 0) red[warp] = su;
    __syncthreads();
    if (warp == 0) {
        float v = red[lane];
#pragma unroll
        for (int o = 16; o; o >>= 1) v += __shfl_xor_sync(0xffffffffu, v, o);
        if (lane == 0) sb[1] = v;
    }
    __syncthreads();
    float rinv = 1.0f / sb[1];
    int len = g_len[b];

    // ---- ctx = rinv * sum_{s<len} e_s v_s + 1e-9 * tail ----
    // 16 partitions x 64 threads; each thread owns 8 h-values (one uint4 of halves)
    int c4 = tid & 63, part = tid >> 6;
    const uint4* v4 = (const uint4*)(g_vh + (size_t)b * Ss * Hh);
    float accf[8];
#pragma unroll
    for (int i = 0; i < 8; i++) accf[i] = 0.0f;
    for (int s = part; s < len; s += 16) {
        float ee = sc[s];
        uint4 v = v4[(size_t)s * 64 + c4];
        const half2* vp = (const half2*)&v;
#pragma unroll
        for (int j = 0; j < 4; j++) {
            float2 vf = __half22float2(vp[j]);
            accf[2 * j]     += ee * vf.x;
            accf[2 * j + 1] += ee * vf.y;
        }
    }
    {
        float4* dst = (float4*)(sctx + part * Hh + c4 * 8);
        dst[0] = make_float4(accf[0], accf[1], accf[2], accf[3]);
        dst[1] = make_float4(accf[4], accf[5], accf[6], accf[7]);
    }
    __syncthreads();
    if (tid < Hh) {
        float v = 0.0f;
#pragma unroll
        for (int p = 0; p < 16; p++) v += sctx[p * Hh + tid];
        g_Xt1[tid * Bb + b] = v * rinv + 1e-9f * g_tail[tid * Bb + b];
    }

    // ---- fc logits ----
    const float4* h14 = (const float4*)sh1;
    for (int v = warp; v < Vv; v += 32) {
        const float4* fw = (const float4*)(fcW + v * Hh);
        float a = 0.0f;
#pragma unroll
        for (int i = 0; i < 4; i++) {
            float4 wv = fw[lane + 32 * i];
            float4 hv = h14[lane + 32 * i];
            a += wv.x * hv.x + wv.y * hv.y + wv.z * hv.z + wv.w * hv.w;
        }
#pragma unroll
        for (int o = 16; o; o >>= 1) a += __shfl_xor_sync(0xffffffffu, a, o);
        if (lane == 0) out[(size_t)b * (Tt * Vv) + t * Vv + v] = a + fcb[v];
    }

    // ---- prefill embedding for next step ----
    if (t < Tt - 1 && tid < Ee) {
        int tok = g_tok[b * Tt + (t + 1)];
        g_Xt1[(512 + tid) * Bb + b] = emb[tok * Ee + tid];
    }
}

// ---------------- host ----------------
extern "C" void kernel_launch(void* const* d_in, const int* in_sizes, int n_in,
                              void* d_out, int out_size) {
    const float* key   = (const float*)d_in[0];
    const float* value = (const float*)d_in[1];
    const void*  dec   = d_in[2];
    const void*  lens  = d_in[3];
    const float* emb   = (const float*)d_in[4];
    const float* Wih1  = (const float*)d_in[5];
    const float* Whh1  = (const float*)d_in[6];
    const float* b1    = (const float*)d_in[7];
    const float* Wih2  = (const float*)d_in[8];
    const float* Whh2  = (const float*)d_in[9];
    const float* b2    = (const float*)d_in[10];
    const float* fcW   = (const float*)d_in[11];
    const float* fcb   = (const float*)d_in[12];
    float* out = (float*)d_out;

    k_setupA<<<2048, 256>>>(dec, lens, Wih1, Whh1, Wih2, Whh2, key, value);
    k_setupB<<<512, 256>>>(key, value, emb);

    for (int t = 0; t < Tt; t++) {
        k_gemm<<<dim3(32, KS1), 256>>>(1);
        k_gate<<<64, 1024>>>(1, b1);
        k_gemm<<<dim3(32, KS2), 256>>>(2);
        k_gate<<<64, 1024>>>(2, b2);
        k_attn<<<Bb, 1024>>>(emb, fcW, fcb, out, t);
    }
}

// round 4
// speedup vs baseline: 1.2734x; 1.0488x over previous
#include <cuda_runtime.h>
#include <cuda_fp16.h>
#include <math.h>

#define Bb 128
#define Ss 800
#define Hh 512
#define Ee 256
#define Vv 34
#define Tt 128
#define KVE (Bb * Ss * Hh)
#define K1d 1280
#define K2d 1024

typedef unsigned int uint32;

// ---------------- persistent device buffers ----------------
__device__ __align__(16) __half g_kh[KVE];                 // key  fp16 [b][s][h]
__device__ __align__(16) __half g_vh[KVE];                 // value fp16 [b][s][h]
__device__ __align__(16) __half g_W1h[2u * 2048 * K1d];    // [hi/lo][r=u*4+g][k]
__device__ __align__(16) __half g_W2h[2u * 2048 * K2d];
__device__ __align__(16) __half g_X1h[(768 + 1024) * Bb];  // rows: 0-511 ctx | 512-767 emb | 768+ h0 (2 slots)
__device__ __align__(16) __half g_X2h[(512 + 1024) * Bb];  // rows: 0-511 h0 | 512+ h1 (2 slots)
__device__ __align__(16) float g_c0[Hh * Bb];
__device__ __align__(16) float g_c1[Hh * Bb];
__device__ __align__(16) float g_h1v[Hh * Bb];
__device__ __align__(16) float g_tail[Hh * Bb];            // sum_{s>=len} value[b,s,h], [h][b]
__device__ int g_tok[Bb * Tt];
__device__ int g_len[Bb];

__device__ __forceinline__ float sigf(float x) { return 1.0f / (1.0f + expf(-x)); }

// ---------------- setup A: tokens/lens + W fp16 hi/lo pack + fp16 KV --------
__global__ void k_setupA(const void* dec, const void* lens,
                         const float* __restrict__ Wih1, const float* __restrict__ Whh1,
                         const float* __restrict__ Wih2, const float* __restrict__ Whh2,
                         const float* __restrict__ key, const float* __restrict__ value) {
    int gtid = blockIdx.x * blockDim.x + threadIdx.x;
    int stride = gridDim.x * blockDim.x;

    if (blockIdx.x == 0) {
        const int* L = (const int*)lens;
        bool is64 = (L[1] == 0 && L[3] == 0 && L[5] == 0 && L[7] == 0);
        for (int i = threadIdx.x; i < Bb; i += blockDim.x)
            g_len[i] = is64 ? (int)((const long long*)lens)[i] : L[i];
        const int* D = (const int*)dec;
        for (int i = threadIdx.x; i < Bb * Tt; i += blockDim.x)
            g_tok[i] = is64 ? (int)((const long long*)dec)[i] : D[i];
    }

    // W1: rows r = u*4+g  <-  original j = g*512+u
    for (int i = gtid; i < 2048 * K1d; i += stride) {
        int r = i / K1d, k = i - r * K1d;
        int u = r >> 2, g = r & 3;
        int j = g * Hh + u;
        float w = (k < 768) ? Wih1[j * 768 + k] : Whh1[j * 512 + (k - 768)];
        __half hi = __float2half_rn(w);
        __half lo = __float2half_rn(w - __half2float(hi));
        g_W1h[i] = hi;
        g_W1h[2048 * K1d + i] = lo;
    }
    for (int i = gtid; i < 2048 * K2d; i += stride) {
        int r = i / K2d, k = i - r * K2d;
        int u = r >> 2, g = r & 3;
        int j = g * Hh + u;
        float w = (k < 512) ? Wih2[j * 512 + k] : Whh2[j * 512 + (k - 512)];
        __half hi = __float2half_rn(w);
        __half lo = __float2half_rn(w - __half2float(hi));
        g_W2h[i] = hi;
        g_W2h[2048 * K2d + i] = lo;
    }

    const float4* k4 = (const float4*)key;
    const float4* v4 = (const float4*)value;
    uint2* kh2 = (uint2*)g_kh;
    uint2* vh2 = (uint2*)g_vh;
    for (int i = gtid; i < KVE / 4; i += stride) {
        float4 kf = k4[i];
        half2 lo = __floats2half2_rn(kf.x, kf.y), hi = __floats2half2_rn(kf.z, kf.w);
        uint2 st; st.x = *(unsigned*)&lo; st.y = *(unsigned*)&hi;
        kh2[i] = st;
        float4 vf = v4[i];
        half2 lo2 = __floats2half2_rn(vf.x, vf.y), hi2 = __floats2half2_rn(vf.z, vf.w);
        uint2 sv; sv.x = *(unsigned*)&lo2; sv.y = *(unsigned*)&hi2;
        vh2[i] = sv;
    }
}

// ---------------- setup B: state init + tail sums ---------------------------
__global__ void k_setupB(const float* __restrict__ key, const float* __restrict__ value,
                         const float* __restrict__ emb) {
    int gtid = blockIdx.x * blockDim.x + threadIdx.x;
    int stride = gridDim.x * blockDim.x;

    // zero h0 slots (X1h rows 768..1791) and all of X2h
    for (int i = gtid; i < 1024 * Bb; i += stride) g_X1h[768 * Bb + i] = __float2half(0.f);
    for (int i = gtid; i < 1536 * Bb; i += stride) g_X2h[i] = __float2half(0.f);

    for (int idx = gtid; idx < Hh * Bb; idx += stride) {
        g_c0[idx] = 0.0f; g_c1[idx] = 0.0f; g_h1v[idx] = 0.0f;
        int b = idx & 127, h = idx >> 7;
        g_X1h[idx] = __float2half_rn(key[(size_t)b * Ss * Hh + h]);  // ctx init
    }
    for (int idx = gtid; idx < Ee * Bb; idx += stride) {
        int b = idx & 127, e = idx >> 7;
        int tok = g_tok[b * Tt + 0];
        g_X1h[(512 + e) * Bb + b] = __float2half_rn(emb[tok * Ee + e]);
    }
    // tail sums
    for (int idx = gtid; idx < Hh * Bb; idx += stride) {
        int h = idx & 511, b = idx >> 9;
        int len = g_len[b];
        float acc = 0.0f;
        const float* vb = value + (size_t)b * Ss * Hh + h;
        for (int s = len; s < Ss; s++) acc += vb[(size_t)s * Hh];
        g_tail[h * Bb + b] = acc;
    }
}

// ---------------- fused LSTM layer: HMMA GEMM (W split hi/lo) + gate --------
// grid 64 blocks x 256 threads. Block: 32 rows (8 u x 4 gates) x 128 b, full K.
__global__ void __launch_bounds__(256) k_lstm(int layer, int slot, const float* __restrict__ bias) {
    const __half* W  = (layer == 1) ? g_W1h : g_W2h;
    const __half* Xa = (layer == 1) ? g_X1h : g_X2h;
    const int split  = (layer == 1) ? 768 : 512;
    const int Kdim   = (layer == 1) ? K1d : K2d;
    const __half* Xb = Xa + (size_t)(split + slot * 512) * Bb;
    const size_t loOff = (size_t)2048 * Kdim;
    float* cst = (layer == 1) ? g_c0 : g_c1;

    int r0 = blockIdx.x * 32;
    int u0 = blockIdx.x * 8;
    int tid = threadIdx.x, lane = tid & 31, warp = tid >> 5;
    int rt = warp >> 2;        // row-tile (16 rows) 0/1
    int ct0 = (warp & 3) * 4;  // 4 col-tiles of 8

    __shared__ __align__(16) char smem[26624];
    __half* Ws0 = (__half*)smem;            // [32][72]
    __half* Ws1 = (__half*)(smem + 4608);   // [32][72]
    __half* Xs  = (__half*)(smem + 9216);   // [64][136]
    float*  Ds  = (float*)smem;             // [32][128] alias (epilogue)

    float acc[4][4];
#pragma unroll
    for (int j = 0; j < 4; j++)
#pragma unroll
        for (int q = 0; q < 4; q++) acc[j][q] = 0.f;

    int wlr = tid >> 3, wq = tid & 7;   // W staging: row, 8-half quad
    int xr = tid >> 4, xq = tid & 15;   // X staging

    // precompute shared addresses for ldmatrix
    unsigned a0addr = (unsigned)__cvta_generic_to_shared(Ws0 + (rt * 16 + (lane & 15)) * 72 + ((lane >> 4) * 8));
    unsigned a1addr = (unsigned)__cvta_generic_to_shared(Ws1 + (rt * 16 + (lane & 15)) * 72 + ((lane >> 4) * 8));
    unsigned bbase  = (unsigned)__cvta_generic_to_shared(Xs + (lane & 15) * 136);

    int nst = Kdim / 64;
    for (int st = 0; st < nst; st++) {
        int k0 = st * 64;
        const __half* wsrc = W + (size_t)(r0 + wlr) * Kdim + k0 + wq * 8;
        *(uint4*)(Ws0 + wlr * 72 + wq * 8) = *(const uint4*)wsrc;
        *(uint4*)(Ws1 + wlr * 72 + wq * 8) = *(const uint4*)(wsrc + loOff);
        const __half* xbase = (k0 < split) ? (Xa + (size_t)k0 * Bb) : (Xb + (size_t)(k0 - split) * Bb);
#pragma unroll
        for (int it = 0; it < 4; it++) {
            int row = xr + 16 * it;
            *(uint4*)(Xs + row * 136 + xq * 8) = *(const uint4*)(xbase + row * Bb + xq * 8);
        }
        __syncthreads();
#pragma unroll
        for (int ki = 0; ki < 4; ki++) {
            int kc = ki * 16;
            uint32 ah[4], al[4];
            asm volatile("ldmatrix.sync.aligned.m8n8.x4.shared.b16 {%0,%1,%2,%3},[%4];"
                         : "=r"(ah[0]), "=r"(ah[1]), "=r"(ah[2]), "=r"(ah[3])
                         : "r"(a0addr + kc * 2));
            asm volatile("ldmatrix.sync.aligned.m8n8.x4.shared.b16 {%0,%1,%2,%3},[%4];"
                         : "=r"(al[0]), "=r"(al[1]), "=r"(al[2]), "=r"(al[3])
                         : "r"(a1addr + kc * 2));
#pragma unroll
            for (int j = 0; j < 4; j++) {
                int n0 = (ct0 + j) * 8;
                uint32 b0, b1;
                asm volatile("ldmatrix.sync.aligned.m8n8.x2.trans.shared.b16 {%0,%1},[%2];"
                             : "=r"(b0), "=r"(b1)
                             : "r"(bbase + (kc * 136 + n0) * 2));
                asm volatile("mma.sync.aligned.m16n8k16.row.col.f32.f16.f16.f32 "
                             "{%0,%1,%2,%3},{%4,%5,%6,%7},{%8,%9},{%0,%1,%2,%3};"
                             : "+f"(acc[j][0]), "+f"(acc[j][1]), "+f"(acc[j][2]), "+f"(acc[j][3])
                             : "r"(ah[0]), "r"(ah[1]), "r"(ah[2]), "r"(ah[3]), "r"(b0), "r"(b1));
                asm volatile("mma.sync.aligned.m16n8k16.row.col.f32.f16.f16.f32 "
                             "{%0,%1,%2,%3},{%4,%5,%6,%7},{%8,%9},{%0,%1,%2,%3};"
                             : "+f"(acc[j][0]), "+f"(acc[j][1]), "+f"(acc[j][2]), "+f"(acc[j][3])
                             : "r"(al[0]), "r"(al[1]), "r"(al[2]), "r"(al[3]), "r"(b0), "r"(b1));
            }
        }
        __syncthreads();
    }

    // epilogue: accs -> smem, then fused gate
#pragma unroll
    for (int j = 0; j < 4; j++) {
        int n0 = (ct0 + j) * 8;
        int row = rt * 16 + (lane >> 2);
        int col = n0 + (lane & 3) * 2;
        *(float2*)(Ds + row * 128 + col) = make_float2(acc[j][0], acc[j][1]);
        *(float2*)(Ds + (row + 8) * 128 + col) = make_float2(acc[j][2], acc[j][3]);
    }
    __syncthreads();
#pragma unroll
    for (int i = 0; i < 4; i++) {
        int idx = tid + 256 * i;
        int b = idx & 127, ul = idx >> 7;
        int u = u0 + ul;
        float gi = Ds[(ul * 4 + 0) * 128 + b] + bias[u];
        float gf = Ds[(ul * 4 + 1) * 128 + b] + bias[512 + u];
        float gg = Ds[(ul * 4 + 2) * 128 + b] + bias[1024 + u];
        float go = Ds[(ul * 4 + 3) * 128 + b] + bias[1536 + u];
        float c = cst[u * Bb + b];
        float cn = sigf(gf) * c + sigf(gi) * tanhf(gg);
        float h = sigf(go) * tanhf(cn);
        cst[u * Bb + b] = cn;
        __half hh = __float2half_rn(h);
        if (layer == 1) {
            g_X2h[u * Bb + b] = hh;                               // h0 for gemm2 (this step)
            g_X1h[(768 + (slot ^ 1) * 512 + u) * Bb + b] = hh;    // h0 for gemm1 (next step)
        } else {
            g_X2h[(512 + (slot ^ 1) * 512 + u) * Bb + b] = hh;    // h1 for gemm2 (next step)
            g_h1v[u * Bb + b] = h;                                // h1 fp32 for attn/fc
        }
    }
}

// ---------------- attention + fc + emb prefill (one block per batch) --------
__global__ void __launch_bounds__(1024) k_attn(
    const float* __restrict__ emb, const float* __restrict__ fcW,
    const float* __restrict__ fcb, float* __restrict__ out, int t)
{
    int b = blockIdx.x;
    int tid = threadIdx.x, lane = tid & 31, warp = tid >> 5;

    __shared__ __align__(16) float sh1[Hh];
    __shared__ __align__(16) half2 sh1h[Hh / 2];
    __shared__ __align__(16) float sc[Ss];
    __shared__ __align__(16) float red[32];
    __shared__ __align__(16) float sb[2];
    __shared__ __align__(16) float sctx[16 * Hh];

    if (tid < Hh) sh1[tid] = g_h1v[tid * Bb + b];
    __syncthreads();
    if (tid < Hh / 2) sh1h[tid] = __floats2half2_rn(sh1[2 * tid], sh1[2 * tid + 1]);
    __syncthreads();

    half2 h1r[2][4];
#pragma unroll
    for (int i = 0; i < 2; i++) {
        const uint4 hv = ((const uint4*)sh1h)[lane + 32 * i];
        h1r[i][0] = *(const half2*)&hv.x; h1r[i][1] = *(const half2*)&hv.y;
        h1r[i][2] = *(const half2*)&hv.z; h1r[i][3] = *(const half2*)&hv.w;
    }

    const uint4* k4 = (const uint4*)(g_kh + (size_t)b * Ss * Hh);
    for (int s = warp; s < Ss; s += 32) {
        const uint4* kr = k4 + (size_t)s * 64;
        float a = 0.0f;
#pragma unroll
        for (int i = 0; i < 2; i++) {
            uint4 kv = kr[lane + 32 * i];
            const half2* kp = (const half2*)&kv;
#pragma unroll
            for (int j = 0; j < 4; j++) {
                float2 kf = __half22float2(kp[j]);
                float2 hf = __half22float2(h1r[i][j]);
                a += kf.x * hf.x + kf.y * hf.y;
            }
        }
#pragma unroll
        for (int o = 16; o; o >>= 1) a += __shfl_xor_sync(0xffffffffu, a, o);
        if (lane == 0) sc[s] = a;
    }
    __syncthreads();

    float m = (tid < Ss) ? sc[tid] : -3.4e38f;
#pragma unroll
    for (int o = 16; o; o >>= 1) m = fmaxf(m, __shfl_xor_sync(0xffffffffu, m, o));
    if (lane == 0) red[warp] = m;
    __syncthreads();
    if (warp == 0) {
        float v = red[lane];
#pragma unroll
        for (int o = 16; o; o >>= 1) v = fmaxf(v, __shfl_xor_sync(0xffffffffu, v, o));
        if (lane == 0) sb[0] = v;
    }
    __syncthreads();
    float mx = sb[0];
    float e = 0.0f;
    if (tid < Ss) { e = expf(sc[tid] - mx); sc[tid] = e; }
    float su = e;
#pragma unroll
    for (int o = 16; o; o >>= 1) su += __shfl_xor_sync(0xffffffffu, su, o);
    __syncthreads();
    if (lane == 0) red[warp] = su;
    __syncthreads();
    if (warp == 0) {
        float v = red[lane];
#pragma unroll
        for (int o = 16; o; o >>= 1) v += __shfl_xor_sync(0xffffffffu, v, o);
        if (lane == 0) sb[1] = v;
    }
    __syncthreads();
    float rinv = 1.0f / sb[1];
    int len = g_len[b];

    int c4 = tid & 63, part = tid >> 6;
    const uint4* v4 = (const uint4*)(g_vh + (size_t)b * Ss * Hh);
    float accf[8];
#pragma unroll
    for (int i = 0; i < 8; i++) accf[i] = 0.0f;
    for (int s = part; s < len; s += 16) {
        float ee = sc[s];
        uint4 v = v4[(size_t)s * 64 + c4];
        const half2* vp = (const half2*)&v;
#pragma unroll
        for (int j = 0; j < 4; j++) {
            float2 vf = __half22float2(vp[j]);
            accf[2 * j]     += ee * vf.x;
            accf[2 * j + 1] += ee * vf.y;
        }
    }
    {
        float4* dst = (float4*)(sctx + part * Hh + c4 * 8);
        dst[0] = make_float4(accf[0], accf[1], accf[2], accf[3]);
        dst[1] = make_float4(accf[4], accf[5], accf[6], accf[7]);
    }
    __syncthreads();
    if (tid < Hh) {
        float v = 0.0f;
#pragma unroll
        for (int p = 0; p < 16; p++) v += sctx[p * Hh + tid];
        float ctx = v * rinv + 1e-9f * g_tail[tid * Bb + b];
        g_X1h[tid * Bb + b] = __float2half_rn(ctx);
    }

    const float4* h14 = (const float4*)sh1;
    for (int v = warp; v < Vv; v += 32) {
        const float4* fw = (const float4*)(fcW + v * Hh);
        float a = 0.0f;
#pragma unroll
        for (int i = 0; i < 4; i++) {
            float4 wv = fw[lane + 32 * i];
            float4 hv = h14[lane + 32 * i];
            a += wv.x * hv.x + wv.y * hv.y + wv.z * hv.z + wv.w * hv.w;
        }
#pragma unroll
        for (int o = 16; o; o >>= 1) a += __shfl_xor_sync(0xffffffffu, a, o);
        if (lane == 0) out[(size_t)b * (Tt * Vv) + t * Vv + v] = a + fcb[v];
    }

    if (t < Tt - 1 && tid < Ee) {
        int tok = g_tok[b * Tt + (t + 1)];
        g_X1h[(512 + tid) * Bb + b] = __float2half_rn(emb[tok * Ee + tid]);
    }
}

// ---------------- host ----------------
extern "C" void kernel_launch(void* const* d_in, const int* in_sizes, int n_in,
                              void* d_out, int out_size) {
    const float* key   = (const float*)d_in[0];
    const float* value = (const float*)d_in[1];
    const void*  dec   = d_in[2];
    const void*  lens  = d_in[3];
    const float* emb   = (const float*)d_in[4];
    const float* Wih1  = (const float*)d_in[5];
    const float* Whh1  = (const float*)d_in[6];
    const float* b1    = (const float*)d_in[7];
    const float* Wih2  = (const float*)d_in[8];
    const float* Whh2  = (const float*)d_in[9];
    const float* b2    = (const float*)d_in[10];
    const float* fcW   = (const float*)d_in[11];
    const float* fcb   = (const float*)d_in[12];
    float* out = (float*)d_out;

    k_setupA<<<2048, 256>>>(dec, lens, Wih1, Whh1, Wih2, Whh2, key, value);
    k_setupB<<<512, 256>>>(key, value, emb);

    for (int t = 0; t < Tt; t++) {
        k_lstm<<<64, 256>>>(1, t & 1, b1);
        k_lstm<<<64, 256>>>(2, t & 1, b2);
        k_attn<<<Bb, 1024>>>(emb, fcW, fcb, out, t);
    }
}

// round 5
// speedup vs baseline: 1.7507x; 1.3747x over previous
#include <cuda_runtime.h>
#include <cuda_fp16.h>
#include <math.h>

#define Bb 128
#define Ss 800
#define Hh 512
#define Ee 256
#define Vv 34
#define Tt 128
#define KVE (Bb * Ss * Hh)
#define K1d 1280
#define K2d 1024
#define STAGE_BYTES 22016   // Whi 2304 + Wlo 2304 + X 17408

typedef unsigned int uint32;

// ---------------- persistent device buffers ----------------
__device__ __align__(16) __half g_kh[KVE];                 // key  fp16 [b][s][h]
__device__ __align__(16) __half g_vh[KVE];                 // value fp16 [b][s][h]
__device__ __align__(16) __half g_W1h[2u * 2048 * K1d];    // [hi/lo][r=u*4+g][k]
__device__ __align__(16) __half g_W2h[2u * 2048 * K2d];
__device__ __align__(16) __half g_X1h[(768 + 1024) * Bb];  // rows: 0-511 ctx | 512-767 emb | 768+ h0 (2 slots)
__device__ __align__(16) __half g_X2h[(512 + 1024) * Bb];  // rows: 0-511 h0 | 512+ h1 (2 slots)
__device__ __align__(16) float g_c0[Hh * Bb];
__device__ __align__(16) float g_c1[Hh * Bb];
__device__ __align__(16) float g_h1v[Hh * Bb];
__device__ __align__(16) float g_tail[Hh * Bb];            // sum_{s>=len} value[b,s,h], [h][b]
__device__ int g_tok[Bb * Tt];
__device__ int g_len[Bb];

__device__ __forceinline__ float sigf(float x) { return 1.0f / (1.0f + expf(-x)); }

__device__ __forceinline__ void cp16(void* dst, const void* src) {
    unsigned d = (unsigned)__cvta_generic_to_shared(dst);
    asm volatile("cp.async.cg.shared.global [%0],[%1],16;\n" :: "r"(d), "l"(src));
}

// ---------------- setup A: tokens/lens + W fp16 hi/lo pack + fp16 KV --------
__global__ void k_setupA(const void* dec, const void* lens,
                         const float* __restrict__ Wih1, const float* __restrict__ Whh1,
                         const float* __restrict__ Wih2, const float* __restrict__ Whh2,
                         const float* __restrict__ key, const float* __restrict__ value) {
    int gtid = blockIdx.x * blockDim.x + threadIdx.x;
    int stride = gridDim.x * blockDim.x;

    if (blockIdx.x == 0) {
        const int* L = (const int*)lens;
        bool is64 = (L[1] == 0 && L[3] == 0 && L[5] == 0 && L[7] == 0);
        for (int i = threadIdx.x; i < Bb; i += blockDim.x)
            g_len[i] = is64 ? (int)((const long long*)lens)[i] : L[i];
        const int* D = (const int*)dec;
        for (int i = threadIdx.x; i < Bb * Tt; i += blockDim.x)
            g_tok[i] = is64 ? (int)((const long long*)dec)[i] : D[i];
    }

    for (int i = gtid; i < 2048 * K1d; i += stride) {
        int r = i / K1d, k = i - r * K1d;
        int u = r >> 2, g = r & 3;
        int j = g * Hh + u;
        float w = (k < 768) ? Wih1[j * 768 + k] : Whh1[j * 512 + (k - 768)];
        __half hi = __float2half_rn(w);
        __half lo = __float2half_rn(w - __half2float(hi));
        g_W1h[i] = hi;
        g_W1h[2048 * K1d + i] = lo;
    }
    for (int i = gtid; i < 2048 * K2d; i += stride) {
        int r = i / K2d, k = i - r * K2d;
        int u = r >> 2, g = r & 3;
        int j = g * Hh + u;
        float w = (k < 512) ? Wih2[j * 512 + k] : Whh2[j * 512 + (k - 512)];
        __half hi = __float2half_rn(w);
        __half lo = __float2half_rn(w - __half2float(hi));
        g_W2h[i] = hi;
        g_W2h[2048 * K2d + i] = lo;
    }

    const float4* k4 = (const float4*)key;
    const float4* v4 = (const float4*)value;
    uint2* kh2 = (uint2*)g_kh;
    uint2* vh2 = (uint2*)g_vh;
    for (int i = gtid; i < KVE / 4; i += stride) {
        float4 kf = k4[i];
        half2 lo = __floats2half2_rn(kf.x, kf.y), hi = __floats2half2_rn(kf.z, kf.w);
        uint2 st; st.x = *(unsigned*)&lo; st.y = *(unsigned*)&hi;
        kh2[i] = st;
        float4 vf = v4[i];
        half2 lo2 = __floats2half2_rn(vf.x, vf.y), hi2 = __floats2half2_rn(vf.z, vf.w);
        uint2 sv; sv.x = *(unsigned*)&lo2; sv.y = *(unsigned*)&hi2;
        vh2[i] = sv;
    }
}

// ---------------- setup B: state init + tail sums ---------------------------
__global__ void k_setupB(const float* __restrict__ key, const float* __restrict__ value,
                         const float* __restrict__ emb) {
    int gtid = blockIdx.x * blockDim.x + threadIdx.x;
    int stride = gridDim.x * blockDim.x;

    for (int i = gtid; i < 1024 * Bb; i += stride) g_X1h[768 * Bb + i] = __float2half(0.f);
    for (int i = gtid; i < 1536 * Bb; i += stride) g_X2h[i] = __float2half(0.f);

    for (int idx = gtid; idx < Hh * Bb; idx += stride) {
        g_c0[idx] = 0.0f; g_c1[idx] = 0.0f; g_h1v[idx] = 0.0f;
        int b = idx & 127, h = idx >> 7;
        g_X1h[idx] = __float2half_rn(key[(size_t)b * Ss * Hh + h]);
    }
    for (int idx = gtid; idx < Ee * Bb; idx += stride) {
        int b = idx & 127, e = idx >> 7;
        int tok = g_tok[b * Tt + 0];
        g_X1h[(512 + e) * Bb + b] = __float2half_rn(emb[tok * Ee + e]);
    }
    for (int idx = gtid; idx < Hh * Bb; idx += stride) {
        int h = idx & 511, b = idx >> 9;
        int len = g_len[b];
        float acc = 0.0f;
        const float* vb = value + (size_t)b * Ss * Hh + h;
        for (int s = len; s < Ss; s++) acc += vb[(size_t)s * Hh];
        g_tail[h * Bb + b] = acc;
    }
}

// ---------------- fused LSTM layer: pipelined HMMA + gate -------------------
// grid 128 blocks x 256 threads. Block: 16 rows (4 u x 4 gates) x 128 b, full K.
// cp.async double-buffered K-pipeline (chunk 64).
__global__ void __launch_bounds__(256) k_lstm(int layer, int slot, const float* __restrict__ bias) {
    const __half* W  = (layer == 1) ? g_W1h : g_W2h;
    const __half* Xa = (layer == 1) ? g_X1h : g_X2h;
    const int split  = (layer == 1) ? 768 : 512;
    const int Kdim   = (layer == 1) ? K1d : K2d;
    const __half* Xb = Xa + (size_t)(split + slot * 512) * Bb;
    const size_t loOff = (size_t)2048 * Kdim;
    float* cst = (layer == 1) ? g_c0 : g_c1;

    int r0 = blockIdx.x * 16;
    int u0 = blockIdx.x * 4;
    int tid = threadIdx.x, lane = tid & 31, warp = tid >> 5;

    // 2 stages x (Whi [16][72] | Wlo [16][72] | X [64][136])
    __shared__ __align__(16) char smem[2 * STAGE_BYTES];
    float* Ds = (float*)smem;  // epilogue alias [16][128]

    float acc[2][4];
#pragma unroll
    for (int j = 0; j < 2; j++)
#pragma unroll
        for (int q = 0; q < 4; q++) acc[j][q] = 0.f;

    const int nst = Kdim / 64;
    int wr = (tid & 127) >> 3, wq = tid & 7;   // W staging
    size_t wsrcOff = (size_t)(r0 + wr) * Kdim + wq * 8 + ((tid >= 128) ? loOff : 0);

    // ---- issue stage st loads ----
    auto issue = [&](int st) {
        int k0 = st * 64;
        char* sb = smem + (st & 1) * STAGE_BYTES;
        __half* sW = (__half*)(sb + ((tid < 128) ? 0 : 2304));
        cp16(sW + wr * 72 + wq * 8, W + wsrcOff + k0);
        __half* sX = (__half*)(sb + 4608);
        const __half* xbase = (k0 < split) ? (Xa + (size_t)k0 * Bb) : (Xb + (size_t)(k0 - split) * Bb);
#pragma unroll
        for (int it = 0; it < 4; it++) {
            int c = tid + 256 * it;
            int r = c >> 4, q = c & 15;
            cp16(sX + r * 136 + q * 8, xbase + r * Bb + q * 8);
        }
        asm volatile("cp.async.commit_group;\n");
    };

    issue(0);
    for (int st = 0; st < nst; st++) {
        if (st + 1 < nst) {
            issue(st + 1);
            asm volatile("cp.async.wait_group 1;\n");
        } else {
            asm volatile("cp.async.wait_group 0;\n");
        }
        __syncthreads();

        char* sb = smem + (st & 1) * STAGE_BYTES;
        __half* Ws0 = (__half*)sb;
        __half* Ws1 = (__half*)(sb + 2304);
        __half* Xs  = (__half*)(sb + 4608);
        unsigned a0addr = (unsigned)__cvta_generic_to_shared(Ws0 + (lane & 15) * 72 + ((lane >> 4) * 8));
        unsigned a1addr = (unsigned)__cvta_generic_to_shared(Ws1 + (lane & 15) * 72 + ((lane >> 4) * 8));
        unsigned bbase  = (unsigned)__cvta_generic_to_shared(Xs + (lane & 15) * 136);

#pragma unroll
        for (int ki = 0; ki < 4; ki++) {
            int kc = ki * 16;
            uint32 ah[4], al[4];
            asm volatile("ldmatrix.sync.aligned.m8n8.x4.shared.b16 {%0,%1,%2,%3},[%4];"
                         : "=r"(ah[0]), "=r"(ah[1]), "=r"(ah[2]), "=r"(ah[3])
                         : "r"(a0addr + kc * 2));
            asm volatile("ldmatrix.sync.aligned.m8n8.x4.shared.b16 {%0,%1,%2,%3},[%4];"
                         : "=r"(al[0]), "=r"(al[1]), "=r"(al[2]), "=r"(al[3])
                         : "r"(a1addr + kc * 2));
#pragma unroll
            for (int j = 0; j < 2; j++) {
                int n0 = warp * 16 + j * 8;
                uint32 b0, b1;
                asm volatile("ldmatrix.sync.aligned.m8n8.x2.trans.shared.b16 {%0,%1},[%2];"
                             : "=r"(b0), "=r"(b1)
                             : "r"(bbase + (kc * 136 + n0) * 2));
                asm volatile("mma.sync.aligned.m16n8k16.row.col.f32.f16.f16.f32 "
                             "{%0,%1,%2,%3},{%4,%5,%6,%7},{%8,%9},{%0,%1,%2,%3};"
                             : "+f"(acc[j][0]), "+f"(acc[j][1]), "+f"(acc[j][2]), "+f"(acc[j][3])
                             : "r"(ah[0]), "r"(ah[1]), "r"(ah[2]), "r"(ah[3]), "r"(b0), "r"(b1));
                asm volatile("mma.sync.aligned.m16n8k16.row.col.f32.f16.f16.f32 "
                             "{%0,%1,%2,%3},{%4,%5,%6,%7},{%8,%9},{%0,%1,%2,%3};"
                             : "+f"(acc[j][0]), "+f"(acc[j][1]), "+f"(acc[j][2]), "+f"(acc[j][3])
                             : "r"(al[0]), "r"(al[1]), "r"(al[2]), "r"(al[3]), "r"(b0), "r"(b1));
            }
        }
        __syncthreads();
    }

    // epilogue: accs -> smem, then fused gate
#pragma unroll
    for (int j = 0; j < 2; j++) {
        int n0 = warp * 16 + j * 8;
        int row = lane >> 2;
        int col = n0 + (lane & 3) * 2;
        *(float2*)(Ds + row * 128 + col)       = make_float2(acc[j][0], acc[j][1]);
        *(float2*)(Ds + (row + 8) * 128 + col) = make_float2(acc[j][2], acc[j][3]);
    }
    __syncthreads();
#pragma unroll
    for (int i = 0; i < 2; i++) {
        int idx = tid + 256 * i;               // 512 = 4u x 128b
        int b = idx & 127, ul = idx >> 7;
        int u = u0 + ul;
        float gi = Ds[(ul * 4 + 0) * 128 + b] + bias[u];
        float gf = Ds[(ul * 4 + 1) * 128 + b] + bias[512 + u];
        float gg = Ds[(ul * 4 + 2) * 128 + b] + bias[1024 + u];
        float go = Ds[(ul * 4 + 3) * 128 + b] + bias[1536 + u];
        float c = cst[u * Bb + b];
        float cn = sigf(gf) * c + sigf(gi) * tanhf(gg);
        float h = sigf(go) * tanhf(cn);
        cst[u * Bb + b] = cn;
        __half hh = __float2half_rn(h);
        if (layer == 1) {
            g_X2h[u * Bb + b] = hh;
            g_X1h[(768 + (slot ^ 1) * 512 + u) * Bb + b] = hh;
        } else {
            g_X2h[(512 + (slot ^ 1) * 512 + u) * Bb + b] = hh;
            g_h1v[u * Bb + b] = h;
        }
    }
}

// ---------------- attention + fc + emb prefill (one block per batch) --------
__global__ void __launch_bounds__(1024) k_attn(
    const float* __restrict__ emb, const float* __restrict__ fcW,
    const float* __restrict__ fcb, float* __restrict__ out, int t)
{
    int b = blockIdx.x;
    int tid = threadIdx.x, lane = tid & 31, warp = tid >> 5;

    __shared__ __align__(16) float sh1[Hh];
    __shared__ __align__(16) half2 sh1h[Hh / 2];
    __shared__ __align__(16) float sc[Ss];
    __shared__ __align__(16) float red[32];
    __shared__ __align__(16) float sb[2];
    __shared__ __align__(16) float sctx[16 * Hh];

    if (tid < Hh) sh1[tid] = g_h1v[tid * Bb + b];
    __syncthreads();
    if (tid < Hh / 2) sh1h[tid] = __floats2half2_rn(sh1[2 * tid], sh1[2 * tid + 1]);
    __syncthreads();

    half2 h1r[2][4];
#pragma unroll
    for (int i = 0; i < 2; i++) {
        const uint4 hv = ((const uint4*)sh1h)[lane + 32 * i];
        h1r[i][0] = *(const half2*)&hv.x; h1r[i][1] = *(const half2*)&hv.y;
        h1r[i][2] = *(const half2*)&hv.z; h1r[i][3] = *(const half2*)&hv.w;
    }

    const uint4* k4 = (const uint4*)(g_kh + (size_t)b * Ss * Hh);
    for (int s = warp; s < Ss; s += 32) {
        const uint4* kr = k4 + (size_t)s * 64;
        float a = 0.0f;
#pragma unroll
        for (int i = 0; i < 2; i++) {
            uint4 kv = kr[lane + 32 * i];
            const half2* kp = (const half2*)&kv;
#pragma unroll
            for (int j = 0; j < 4; j++) {
                float2 kf = __half22float2(kp[j]);
                float2 hf = __half22float2(h1r[i][j]);
                a += kf.x * hf.x + kf.y * hf.y;
            }
        }
#pragma unroll
        for (int o = 16; o; o >>= 1) a += __shfl_xor_sync(0xffffffffu, a, o);
        if (lane == 0) sc[s] = a;
    }
    __syncthreads();

    float m = (tid < Ss) ? sc[tid] : -3.4e38f;
#pragma unroll
    for (int o = 16; o; o >>= 1) m = fmaxf(m, __shfl_xor_sync(0xffffffffu, m, o));
    if (lane == 0) red[warp] = m;
    __syncthreads();
    if (warp == 0) {
        float v = red[lane];
#pragma unroll
        for (int o = 16; o; o >>= 1) v = fmaxf(v, __shfl_xor_sync(0xffffffffu, v, o));
        if (lane == 0) sb[0] = v;
    }
    __syncthreads();
    float mx = sb[0];
    float e = 0.0f;
    if (tid < Ss) { e = expf(sc[tid] - mx); sc[tid] = e; }
    float su = e;
#pragma unroll
    for (int o = 16; o; o >>= 1) su += __shfl_xor_sync(0xffffffffu, su, o);
    __syncthreads();
    if (lane == 0) red[warp] = su;
    __syncthreads();
    if (warp == 0) {
        float v = red[lane];
#pragma unroll
        for (int o = 16; o; o >>= 1) v += __shfl_xor_sync(0xffffffffu, v, o);
        if (lane == 0) sb[1] = v;
    }
    __syncthreads();
    float rinv = 1.0f / sb[1];
    int len = g_len[b];

    int c4 = tid & 63, part = tid >> 6;
    const uint4* v4 = (const uint4*)(g_vh + (size_t)b * Ss * Hh);
    float accf[8];
#pragma unroll
    for (int i = 0; i < 8; i++) accf[i] = 0.0f;
    for (int s = part; s < len; s += 16) {
        float ee = sc[s];
        uint4 v = v4[(size_t)s * 64 + c4];
        const half2* vp = (const half2*)&v;
#pragma unroll
        for (int j = 0; j < 4; j++) {
            float2 vf = __half22float2(vp[j]);
            accf[2 * j]     += ee * vf.x;
            accf[2 * j + 1] += ee * vf.y;
        }
    }
    {
        float4* dst = (float4*)(sctx + part * Hh + c4 * 8);
        dst[0] = make_float4(accf[0], accf[1], accf[2], accf[3]);
        dst[1] = make_float4(accf[4], accf[5], accf[6], accf[7]);
    }
    __syncthreads();
    if (tid < Hh) {
        float v = 0.0f;
#pragma unroll
        for (int p = 0; p < 16; p++) v += sctx[p * Hh + tid];
        float ctx = v * rinv + 1e-9f * g_tail[tid * Bb + b];
        g_X1h[tid * Bb + b] = __float2half_rn(ctx);
    }

    const float4* h14 = (const float4*)sh1;
    for (int v = warp; v < Vv; v += 32) {
        const float4* fw = (const float4*)(fcW + v * Hh);
        float a = 0.0f;
#pragma unroll
        for (int i = 0; i < 4; i++) {
            float4 wv = fw[lane + 32 * i];
            float4 hv = h14[lane + 32 * i];
            a += wv.x * hv.x + wv.y * hv.y + wv.z * hv.z + wv.w * hv.w;
        }
#pragma unroll
        for (int o = 16; o; o >>= 1) a += __shfl_xor_sync(0xffffffffu, a, o);
        if (lane == 0) out[(size_t)b * (Tt * Vv) + t * Vv + v] = a + fcb[v];
    }

    if (t < Tt - 1 && tid < Ee) {
        int tok = g_tok[b * Tt + (t + 1)];
        g_X1h[(512 + tid) * Bb + b] = __float2half_rn(emb[tok * Ee + tid]);
    }
}

// ---------------- host ----------------
extern "C" void kernel_launch(void* const* d_in, const int* in_sizes, int n_in,
                              void* d_out, int out_size) {
    const float* key   = (const float*)d_in[0];
    const float* value = (const float*)d_in[1];
    const void*  dec   = d_in[2];
    const void*  lens  = d_in[3];
    const float* emb   = (const float*)d_in[4];
    const float* Wih1  = (const float*)d_in[5];
    const float* Whh1  = (const float*)d_in[6];
    const float* b1    = (const float*)d_in[7];
    const float* Wih2  = (const float*)d_in[8];
    const float* Whh2  = (const float*)d_in[9];
    const float* b2    = (const float*)d_in[10];
    const float* fcW   = (const float*)d_in[11];
    const float* fcb   = (const float*)d_in[12];
    float* out = (float*)d_out;

    k_setupA<<<2048, 256>>>(dec, lens, Wih1, Whh1, Wih2, Whh2, key, value);
    k_setupB<<<512, 256>>>(key, value, emb);

    for (int t = 0; t < Tt; t++) {
        k_lstm<<<128, 256>>>(1, t & 1, b1);
        k_lstm<<<128, 256>>>(2, t & 1, b2);
        k_attn<<<Bb, 1024>>>(emb, fcW, fcb, out, t);
    }
}

// round 6
// speedup vs baseline: 1.9312x; 1.1031x over previous
#include <cuda_runtime.h>
#include <cuda_fp16.h>
#include <math.h>

#define Bb 128
#define Ss 800
#define Hh 512
#define Ee 256
#define Vv 34
#define Tt 128
#define KVE (Bb * Ss * Hh)
#define K1d 1280
#define K2d 1024
#define STGB 22016           // per-wg stage: Whi 2304 + Wlo 2304 + X 17408
#define DYNB (4 * 2 * STGB)  // 176128 bytes dynamic smem

typedef unsigned int uint32;

// ---------------- persistent device buffers ----------------
__device__ __align__(16) __half g_kh[KVE];
__device__ __align__(16) __half g_vh[KVE];
__device__ __align__(16) __half g_W1h[2u * 2048 * K1d];    // [hi/lo][r=u*4+g][k]
__device__ __align__(16) __half g_W2h[2u * 2048 * K2d];
__device__ __align__(16) __half g_X1h[(768 + 1024) * Bb];  // ctx | emb | h0 x2 slots
__device__ __align__(16) __half g_X2h[(512 + 1024) * Bb];  // h0 | h1 x2 slots
__device__ __align__(16) float g_c0[Hh * Bb];
__device__ __align__(16) float g_c1[Hh * Bb];
__device__ __align__(16) float g_h1v[Hh * Bb];
__device__ __align__(16) float g_tail[Hh * Bb];
__device__ int g_tok[Bb * Tt];
__device__ int g_len[Bb];
__device__ unsigned g_bar_count;
__device__ volatile unsigned g_bar_gen;

__device__ __forceinline__ float sigf(float x) { return 1.0f / (1.0f + expf(-x)); }

__device__ __forceinline__ void cp16(void* dst, const void* src) {
    unsigned d = (unsigned)__cvta_generic_to_shared(dst);
    asm volatile("cp.async.cg.shared.global [%0],[%1],16;\n" :: "r"(d), "l"(src));
}

__device__ __forceinline__ void gridbar() {
    __syncthreads();
    if (threadIdx.x == 0) {
        __threadfence();
        unsigned gen = g_bar_gen;
        if (atomicAdd(&g_bar_count, 1u) == gridDim.x - 1) {
            g_bar_count = 0;
            __threadfence();
            g_bar_gen = gen + 1;
        } else {
            while (g_bar_gen == gen) __nanosleep(32);
        }
    }
    __syncthreads();
}

// ---------------- setup A ----------------
__global__ void k_setupA(const void* dec, const void* lens,
                         const float* __restrict__ Wih1, const float* __restrict__ Whh1,
                         const float* __restrict__ Wih2, const float* __restrict__ Whh2,
                         const float* __restrict__ key, const float* __restrict__ value) {
    int gtid = blockIdx.x * blockDim.x + threadIdx.x;
    int stride = gridDim.x * blockDim.x;

    if (gtid == 0) { g_bar_count = 0; g_bar_gen = 0; }
    if (blockIdx.x == 0) {
        const int* L = (const int*)lens;
        bool is64 = (L[1] == 0 && L[3] == 0 && L[5] == 0 && L[7] == 0);
        for (int i = threadIdx.x; i < Bb; i += blockDim.x)
            g_len[i] = is64 ? (int)((const long long*)lens)[i] : L[i];
        const int* D = (const int*)dec;
        for (int i = threadIdx.x; i < Bb * Tt; i += blockDim.x)
            g_tok[i] = is64 ? (int)((const long long*)dec)[i] : D[i];
    }

    for (int i = gtid; i < 2048 * K1d; i += stride) {
        int r = i / K1d, k = i - r * K1d;
        int u = r >> 2, g = r & 3;
        int j = g * Hh + u;
        float w = (k < 768) ? Wih1[j * 768 + k] : Whh1[j * 512 + (k - 768)];
        __half hi = __float2half_rn(w);
        __half lo = __float2half_rn(w - __half2float(hi));
        g_W1h[i] = hi;
        g_W1h[2048 * K1d + i] = lo;
    }
    for (int i = gtid; i < 2048 * K2d; i += stride) {
        int r = i / K2d, k = i - r * K2d;
        int u = r >> 2, g = r & 3;
        int j = g * Hh + u;
        float w = (k < 512) ? Wih2[j * 512 + k] : Whh2[j * 512 + (k - 512)];
        __half hi = __float2half_rn(w);
        __half lo = __float2half_rn(w - __half2float(hi));
        g_W2h[i] = hi;
        g_W2h[2048 * K2d + i] = lo;
    }

    const float4* k4 = (const float4*)key;
    const float4* v4 = (const float4*)value;
    uint2* kh2 = (uint2*)g_kh;
    uint2* vh2 = (uint2*)g_vh;
    for (int i = gtid; i < KVE / 4; i += stride) {
        float4 kf = k4[i];
        half2 lo = __floats2half2_rn(kf.x, kf.y), hi = __floats2half2_rn(kf.z, kf.w);
        uint2 st; st.x = *(unsigned*)&lo; st.y = *(unsigned*)&hi;
        kh2[i] = st;
        float4 vf = v4[i];
        half2 lo2 = __floats2half2_rn(vf.x, vf.y), hi2 = __floats2half2_rn(vf.z, vf.w);
        uint2 sv; sv.x = *(unsigned*)&lo2; sv.y = *(unsigned*)&hi2;
        vh2[i] = sv;
    }
}

// ---------------- setup B ----------------
__global__ void k_setupB(const float* __restrict__ key, const float* __restrict__ value,
                         const float* __restrict__ emb) {
    int gtid = blockIdx.x * blockDim.x + threadIdx.x;
    int stride = gridDim.x * blockDim.x;

    for (int i = gtid; i < 1024 * Bb; i += stride) g_X1h[768 * Bb + i] = __float2half(0.f);
    for (int i = gtid; i < 1536 * Bb; i += stride) g_X2h[i] = __float2half(0.f);

    for (int idx = gtid; idx < Hh * Bb; idx += stride) {
        g_c0[idx] = 0.0f; g_c1[idx] = 0.0f; g_h1v[idx] = 0.0f;
        int b = idx & 127, h = idx >> 7;
        g_X1h[idx] = __float2half_rn(key[(size_t)b * Ss * Hh + h]);
    }
    for (int idx = gtid; idx < Ee * Bb; idx += stride) {
        int b = idx & 127, e = idx >> 7;
        int tok = g_tok[b * Tt + 0];
        g_X1h[(512 + e) * Bb + b] = __float2half_rn(emb[tok * Ee + e]);
    }
    for (int idx = gtid; idx < Hh * Bb; idx += stride) {
        int h = idx & 511, b = idx >> 9;
        int len = g_len[b];
        float acc = 0.0f;
        const float* vb = value + (size_t)b * Ss * Hh + h;
        for (int s = len; s < Ss; s++) acc += vb[(size_t)s * Hh];
        g_tail[h * Bb + b] = acc;
    }
}

// ---------------- persistent mega-kernel ----------------
// 128 blocks x 1024 threads. LSTM: block covers 16 rows (4u x 4 gates) x 128 b;
// 4 warpgroups split K; smem reduce + fused gate. ATTN: block = one batch.
__global__ void __launch_bounds__(1024, 1) k_loop(
    const float* __restrict__ emb, const float* __restrict__ fcW,
    const float* __restrict__ fcb, const float* __restrict__ bias1,
    const float* __restrict__ bias2, float* __restrict__ out)
{
    extern __shared__ __align__(16) char dyn[];
    int tid = threadIdx.x;
    int blk = blockIdx.x;

    // ---- lstm lambda ----
    auto lstm_phase = [&](int layer, int slot, const float* bias) {
        const __half* W  = (layer == 1) ? g_W1h : g_W2h;
        const __half* Xa = (layer == 1) ? g_X1h : g_X2h;
        const int split  = (layer == 1) ? 768 : 512;
        const int Kdim   = (layer == 1) ? K1d : K2d;
        const __half* Xb = Xa + (size_t)(split + slot * 512) * Bb;
        const size_t loOff = (size_t)2048 * Kdim;
        float* cst = (layer == 1) ? g_c0 : g_c1;

        int r0 = blk * 16;
        int u0 = blk * 4;
        int wg = tid >> 8;          // warpgroup 0-3
        int wt = tid & 255;
        int lane = wt & 31, w8 = wt >> 5;
        int Kwg = Kdim >> 2;
        int wgK0 = wg * Kwg;
        char* sbase = dyn + wg * 2 * STGB;

        float acc[2][4];
#pragma unroll
        for (int j = 0; j < 2; j++)
#pragma unroll
            for (int q = 0; q < 4; q++) acc[j][q] = 0.f;

        int wr = (wt & 127) >> 3, wq = wt & 7;
        size_t wsrcOff = (size_t)(r0 + wr) * Kdim + wq * 8 + ((wt >= 128) ? loOff : 0);
        int nst = Kwg >> 6;  // 5 or 4

        auto issue = [&](int st) {
            int k0 = wgK0 + st * 64;
            char* sb = sbase + (st & 1) * STGB;
            __half* sW = (__half*)(sb + ((wt < 128) ? 0 : 2304));
            cp16(sW + wr * 72 + wq * 8, W + wsrcOff + k0);
            __half* sX = (__half*)(sb + 4608);
            const __half* xbase = (k0 < split) ? (Xa + (size_t)k0 * Bb) : (Xb + (size_t)(k0 - split) * Bb);
#pragma unroll
            for (int it = 0; it < 4; it++) {
                int c = wt + 256 * it;
                int r = c >> 4, q = c & 15;
                cp16(sX + r * 136 + q * 8, xbase + r * Bb + q * 8);
            }
            asm volatile("cp.async.commit_group;\n");
        };

        issue(0);
        for (int st = 0; st < nst; st++) {
            if (st + 1 < nst) {
                issue(st + 1);
                asm volatile("cp.async.wait_group 1;\n");
            } else {
                asm volatile("cp.async.wait_group 0;\n");
            }
            asm volatile("bar.sync %0, 256;" :: "r"(wg + 1) : "memory");

            char* sb = sbase + (st & 1) * STGB;
            __half* Ws0 = (__half*)sb;
            __half* Ws1 = (__half*)(sb + 2304);
            __half* Xs  = (__half*)(sb + 4608);
            unsigned a0addr = (unsigned)__cvta_generic_to_shared(Ws0 + (lane & 15) * 72 + ((lane >> 4) * 8));
            unsigned a1addr = (unsigned)__cvta_generic_to_shared(Ws1 + (lane & 15) * 72 + ((lane >> 4) * 8));
            unsigned bbase  = (unsigned)__cvta_generic_to_shared(Xs + (lane & 15) * 136);

#pragma unroll
            for (int ki = 0; ki < 4; ki++) {
                int kc = ki * 16;
                uint32 ah[4], al[4];
                asm volatile("ldmatrix.sync.aligned.m8n8.x4.shared.b16 {%0,%1,%2,%3},[%4];"
                             : "=r"(ah[0]), "=r"(ah[1]), "=r"(ah[2]), "=r"(ah[3])
                             : "r"(a0addr + kc * 2));
                asm volatile("ldmatrix.sync.aligned.m8n8.x4.shared.b16 {%0,%1,%2,%3},[%4];"
                             : "=r"(al[0]), "=r"(al[1]), "=r"(al[2]), "=r"(al[3])
                             : "r"(a1addr + kc * 2));
#pragma unroll
                for (int j = 0; j < 2; j++) {
                    int n0 = w8 * 16 + j * 8;
                    uint32 b0, b1;
                    asm volatile("ldmatrix.sync.aligned.m8n8.x2.trans.shared.b16 {%0,%1},[%2];"
                                 : "=r"(b0), "=r"(b1)
                                 : "r"(bbase + (kc * 136 + n0) * 2));
                    asm volatile("mma.sync.aligned.m16n8k16.row.col.f32.f16.f16.f32 "
                                 "{%0,%1,%2,%3},{%4,%5,%6,%7},{%8,%9},{%0,%1,%2,%3};"
                                 : "+f"(acc[j][0]), "+f"(acc[j][1]), "+f"(acc[j][2]), "+f"(acc[j][3])
                                 : "r"(ah[0]), "r"(ah[1]), "r"(ah[2]), "r"(ah[3]), "r"(b0), "r"(b1));
                    asm volatile("mma.sync.aligned.m16n8k16.row.col.f32.f16.f16.f32 "
                                 "{%0,%1,%2,%3},{%4,%5,%6,%7},{%8,%9},{%0,%1,%2,%3};"
                                 : "+f"(acc[j][0]), "+f"(acc[j][1]), "+f"(acc[j][2]), "+f"(acc[j][3])
                                 : "r"(al[0]), "r"(al[1]), "r"(al[2]), "r"(al[3]), "r"(b0), "r"(b1));
                }
            }
            asm volatile("bar.sync %0, 256;" :: "r"(wg + 1) : "memory");
        }

        // whole block done reading stage buffers -> safe to alias partial buffers
        __syncthreads();
        float* P = (float*)dyn;  // [wg][16][128]
#pragma unroll
        for (int j = 0; j < 2; j++) {
            int n0 = w8 * 16 + j * 8;
            int row = lane >> 2;
            int col = n0 + (lane & 3) * 2;
            *(float2*)(P + wg * 2048 + row * 128 + col)       = make_float2(acc[j][0], acc[j][1]);
            *(float2*)(P + wg * 2048 + (row + 8) * 128 + col) = make_float2(acc[j][2], acc[j][3]);
        }
        __syncthreads();
        if (tid < 512) {
            int b = tid & 127, ul = tid >> 7;
            int u = u0 + ul;
            float gv[4];
#pragma unroll
            for (int g = 0; g < 4; g++) {
                int r = (ul * 4 + g) * 128 + b;
                gv[g] = P[r] + P[2048 + r] + P[4096 + r] + P[6144 + r] + bias[g * Hh + u];
            }
            float c = cst[u * Bb + b];
            float cn = sigf(gv[1]) * c + sigf(gv[0]) * tanhf(gv[2]);
            float h = sigf(gv[3]) * tanhf(cn);
            cst[u * Bb + b] = cn;
            __half hh = __float2half_rn(h);
            if (layer == 1) {
                g_X2h[u * Bb + b] = hh;
                g_X1h[(768 + (slot ^ 1) * 512 + u) * Bb + b] = hh;
            } else {
                g_X2h[(512 + (slot ^ 1) * 512 + u) * Bb + b] = hh;
                g_h1v[u * Bb + b] = h;
            }
        }
        __syncthreads();
    };

    // ---- attn smem layout ----
    float* sh1  = (float*)dyn;            // 2048 B
    half2* sh1h = (half2*)(dyn + 2048);   // 512 B
    float* sc   = (float*)(dyn + 2560);   // 3200 B
    float* red  = (float*)(dyn + 5760);   // 128 B
    float* sb2  = (float*)(dyn + 5888);   // 8 B
    float* sctx = (float*)(dyn + 6144);   // 32768 B

    for (int t = 0; t < Tt; t++) {
        int slot = t & 1;
        lstm_phase(1, slot, bias1);
        gridbar();
        lstm_phase(2, slot, bias2);
        gridbar();

        // ================= ATTN phase: block = batch =================
        {
            int b = blk;
            int lane = tid & 31, warp = tid >> 5;

            if (tid < Hh) sh1[tid] = __ldcg(&g_h1v[tid * Bb + b]);
            __syncthreads();
            if (tid < Hh / 2) sh1h[tid] = __floats2half2_rn(sh1[2 * tid], sh1[2 * tid + 1]);
            __syncthreads();

            half2 h1r[2][4];
#pragma unroll
            for (int i = 0; i < 2; i++) {
                const uint4 hv = ((const uint4*)sh1h)[lane + 32 * i];
                h1r[i][0] = *(const half2*)&hv.x; h1r[i][1] = *(const half2*)&hv.y;
                h1r[i][2] = *(const half2*)&hv.z; h1r[i][3] = *(const half2*)&hv.w;
            }

            const uint4* k4 = (const uint4*)(g_kh + (size_t)b * Ss * Hh);
            for (int s = warp; s < Ss; s += 32) {
                const uint4* kr = k4 + (size_t)s * 64;
                float a = 0.0f;
#pragma unroll
                for (int i = 0; i < 2; i++) {
                    uint4 kv = kr[lane + 32 * i];
                    const half2* kp = (const half2*)&kv;
#pragma unroll
                    for (int j = 0; j < 4; j++) {
                        float2 kf = __half22float2(kp[j]);
                        float2 hf = __half22float2(h1r[i][j]);
                        a += kf.x * hf.x + kf.y * hf.y;
                    }
                }
#pragma unroll
                for (int o = 16; o; o >>= 1) a += __shfl_xor_sync(0xffffffffu, a, o);
                if (lane == 0) sc[s] = a;
            }
            __syncthreads();

            float m = (tid < Ss) ? sc[tid] : -3.4e38f;
#pragma unroll
            for (int o = 16; o; o >>= 1) m = fmaxf(m, __shfl_xor_sync(0xffffffffu, m, o));
            if (lane == 0) red[warp] = m;
            __syncthreads();
            if (warp == 0) {
                float v = red[lane];
#pragma unroll
                for (int o = 16; o; o >>= 1) v = fmaxf(v, __shfl_xor_sync(0xffffffffu, v, o));
                if (lane == 0) sb2[0] = v;
            }
            __syncthreads();
            float mx = sb2[0];
            float e = 0.0f;
            if (tid < Ss) { e = expf(sc[tid] - mx); sc[tid] = e; }
            float su = e;
#pragma unroll
            for (int o = 16; o; o >>= 1) su += __shfl_xor_sync(0xffffffffu, su, o);
            __syncthreads();
            if (lane == 0) red[warp] = su;
            __syncthreads();
            if (warp == 0) {
                float v = red[lane];
#pragma unroll
                for (int o = 16; o; o >>= 1) v += __shfl_xor_sync(0xffffffffu, v, o);
                if (lane == 0) sb2[1] = v;
            }
            __syncthreads();
            float rinv = 1.0f / sb2[1];
            int len = g_len[b];

            int c4 = tid & 63, part = tid >> 6;
            const uint4* v4 = (const uint4*)(g_vh + (size_t)b * Ss * Hh);
            float accf[8];
#pragma unroll
            for (int i = 0; i < 8; i++) accf[i] = 0.0f;
            for (int s = part; s < len; s += 16) {
                float ee = sc[s];
                uint4 v = v4[(size_t)s * 64 + c4];
                const half2* vp = (const half2*)&v;
#pragma unroll
                for (int j = 0; j < 4; j++) {
                    float2 vf = __half22float2(vp[j]);
                    accf[2 * j]     += ee * vf.x;
                    accf[2 * j + 1] += ee * vf.y;
                }
            }
            {
                float4* dst = (float4*)(sctx + part * Hh + c4 * 8);
                dst[0] = make_float4(accf[0], accf[1], accf[2], accf[3]);
                dst[1] = make_float4(accf[4], accf[5], accf[6], accf[7]);
            }
            __syncthreads();
            if (tid < Hh) {
                float v = 0.0f;
#pragma unroll
                for (int p = 0; p < 16; p++) v += sctx[p * Hh + tid];
                float ctx = v * rinv + 1e-9f * g_tail[tid * Bb + b];
                g_X1h[tid * Bb + b] = __float2half_rn(ctx);
            }

            const float4* h14 = (const float4*)sh1;
            for (int v = warp; v < Vv; v += 32) {
                const float4* fw = (const float4*)(fcW + v * Hh);
                float a = 0.0f;
#pragma unroll
                for (int i = 0; i < 4; i++) {
                    float4 wv = fw[lane + 32 * i];
                    float4 hv = h14[lane + 32 * i];
                    a += wv.x * hv.x + wv.y * hv.y + wv.z * hv.z + wv.w * hv.w;
                }
#pragma unroll
                for (int o = 16; o; o >>= 1) a += __shfl_xor_sync(0xffffffffu, a, o);
                if (lane == 0) out[(size_t)b * (Tt * Vv) + t * Vv + v] = a + fcb[v];
            }

            if (t < Tt - 1 && tid < Ee) {
                int tok = g_tok[b * Tt + (t + 1)];
                g_X1h[(512 + tid) * Bb + b] = __float2half_rn(emb[tok * Ee + tid]);
            }
        }
        gridbar();
    }
}

// ---------------- host ----------------
extern "C" void kernel_launch(void* const* d_in, const int* in_sizes, int n_in,
                              void* d_out, int out_size) {
    const float* key   = (const float*)d_in[0];
    const float* value = (const float*)d_in[1];
    const void*  dec   = d_in[2];
    const void*  lens  = d_in[3];
    const float* emb   = (const float*)d_in[4];
    const float* Wih1  = (const float*)d_in[5];
    const float* Whh1  = (const float*)d_in[6];
    const float* b1    = (const float*)d_in[7];
    const float* Wih2  = (const float*)d_in[8];
    const float* Whh2  = (const float*)d_in[9];
    const float* b2    = (const float*)d_in[10];
    const float* fcW   = (const float*)d_in[11];
    const float* fcb   = (const float*)d_in[12];
    float* out = (float*)d_out;

    static bool attrSet = false;
    if (!attrSet) {
        cudaFuncSetAttribute(k_loop, cudaFuncAttributeMaxDynamicSharedMemorySize, DYNB);
        attrSet = true;
    }

    k_setupA<<<2048, 256>>>(dec, lens, Wih1, Whh1, Wih2, Whh2, key, value);
    k_setupB<<<512, 256>>>(key, value, emb);
    k_loop<<<Bb, 1024, DYNB>>>(emb, fcW, fcb, b1, b2, out);
}

// round 7
// speedup vs baseline: 1.9596x; 1.0147x over previous
#include <cuda_runtime.h>
#include <cuda_fp16.h>
#include <math.h>

#define Bb 128
#define Ss 800
#define Hh 512
#define Ee 256
#define Vv 34
#define Tt 128
#define KVE (Bb * Ss * Hh)
#define K1d 1280
#define K2d 1024
// smem layout: W chunks [0, 82944) | X staging / attn scratch [82944, 222208)
#define WB 82944            // 36 chunks * 2304 B (chunk = 16 rows x 72 halves)
#define XSTG 17408          // one X stage: 64k x 136 halves x 2B
#define DYNB (WB + 4 * 2 * XSTG)   // 222208

typedef unsigned int uint32;

// ---------------- persistent device buffers ----------------
__device__ __align__(16) __half g_kh[KVE];
__device__ __align__(16) __half g_vh[KVE];
__device__ __align__(16) __half g_W1h[2048 * K1d];         // [r=u*4+g][k] fp16
__device__ __align__(16) __half g_W2h[2048 * K2d];
__device__ __align__(16) __half g_X1h[(768 + 1024) * Bb];  // ctx | emb | h0 x2 slots
__device__ __align__(16) __half g_X2h[(512 + 1024) * Bb];  // h0 | h1 x2 slots
__device__ __align__(16) float g_c0[Hh * Bb];
__device__ __align__(16) float g_c1[Hh * Bb];
__device__ __align__(16) float g_h1t[Bb * Hh];             // h1 fp32 [b][h] (coalesced for attn)
__device__ __align__(16) float g_tail[Hh * Bb];
__device__ int g_tok[Bb * Tt];
__device__ int g_len[Bb];
__device__ unsigned g_bar_count;
__device__ volatile unsigned g_bar_gen;

__device__ __forceinline__ float sigf(float x) { return 1.0f / (1.0f + expf(-x)); }

__device__ __forceinline__ void cp16(void* dst, const void* src) {
    unsigned d = (unsigned)__cvta_generic_to_shared(dst);
    asm volatile("cp.async.cg.shared.global [%0],[%1],16;\n" :: "r"(d), "l"(src));
}

__device__ __forceinline__ void gridbar() {
    __syncthreads();
    if (threadIdx.x == 0) {
        __threadfence();
        unsigned gen = g_bar_gen;
        if (atomicAdd(&g_bar_count, 1u) == gridDim.x - 1) {
            g_bar_count = 0;
            __threadfence();
            g_bar_gen = gen + 1;
        } else {
            while (g_bar_gen == gen) __nanosleep(16);
        }
    }
    __syncthreads();
}

// ---------------- single setup kernel (all init, no cross-block deps) -------
__global__ void k_setup(const void* dec, const void* lens,
                        const float* __restrict__ Wih1, const float* __restrict__ Whh1,
                        const float* __restrict__ Wih2, const float* __restrict__ Whh2,
                        const float* __restrict__ key, const float* __restrict__ value,
                        const float* __restrict__ emb) {
    int gtid = blockIdx.x * blockDim.x + threadIdx.x;
    int stride = gridDim.x * blockDim.x;

    const int* L = (const int*)lens;
    bool is64 = (L[1] == 0 && L[3] == 0 && L[5] == 0 && L[7] == 0);

    if (gtid == 0) { g_bar_count = 0; g_bar_gen = 0; }
    if (blockIdx.x == 0) {
        for (int i = threadIdx.x; i < Bb; i += blockDim.x)
            g_len[i] = is64 ? (int)((const long long*)lens)[i] : L[i];
        const int* D = (const int*)dec;
        for (int i = threadIdx.x; i < Bb * Tt; i += blockDim.x)
            g_tok[i] = is64 ? (int)((const long long*)dec)[i] : D[i];
    }

    for (int i = gtid; i < 2048 * K1d; i += stride) {
        int r = i / K1d, k = i - r * K1d;
        int u = r >> 2, g = r & 3;
        int j = g * Hh + u;
        float w = (k < 768) ? Wih1[j * 768 + k] : Whh1[j * 512 + (k - 768)];
        g_W1h[i] = __float2half_rn(w);
    }
    for (int i = gtid; i < 2048 * K2d; i += stride) {
        int r = i / K2d, k = i - r * K2d;
        int u = r >> 2, g = r & 3;
        int j = g * Hh + u;
        float w = (k < 512) ? Wih2[j * 512 + k] : Whh2[j * 512 + (k - 512)];
        g_W2h[i] = __float2half_rn(w);
    }

    const float4* k4 = (const float4*)key;
    const float4* v4 = (const float4*)value;
    uint2* kh2 = (uint2*)g_kh;
    uint2* vh2 = (uint2*)g_vh;
    for (int i = gtid; i < KVE / 4; i += stride) {
        float4 kf = k4[i];
        half2 lo = __floats2half2_rn(kf.x, kf.y), hi = __floats2half2_rn(kf.z, kf.w);
        uint2 st; st.x = *(unsigned*)&lo; st.y = *(unsigned*)&hi;
        kh2[i] = st;
        float4 vf = v4[i];
        half2 lo2 = __floats2half2_rn(vf.x, vf.y), hi2 = __floats2half2_rn(vf.z, vf.w);
        uint2 sv; sv.x = *(unsigned*)&lo2; sv.y = *(unsigned*)&hi2;
        vh2[i] = sv;
    }

    // state init
    for (int i = gtid; i < 1024 * Bb; i += stride) g_X1h[768 * Bb + i] = __float2half(0.f);
    for (int i = gtid; i < 1536 * Bb; i += stride) g_X2h[i] = __float2half(0.f);
    for (int idx = gtid; idx < Hh * Bb; idx += stride) {
        g_c0[idx] = 0.0f; g_c1[idx] = 0.0f; g_h1t[idx] = 0.0f;
        int b = idx & 127, h = idx >> 7;
        g_X1h[idx] = __float2half_rn(key[(size_t)b * Ss * Hh + h]);  // ctx init
    }
    for (int idx = gtid; idx < Ee * Bb; idx += stride) {
        int b = idx & 127, e = idx >> 7;
        long long tok = is64 ? ((const long long*)dec)[b * Tt] : (long long)((const int*)dec)[b * Tt];
        g_X1h[(512 + e) * Bb + b] = __float2half_rn(emb[(int)tok * Ee + e]);
    }
    // tail sums (len derived inline, no dependency on g_len)
    for (int idx = gtid; idx < Hh * Bb; idx += stride) {
        int h = idx & 511, b = idx >> 9;
        int len = is64 ? (int)((const long long*)lens)[b] : L[b];
        float acc = 0.0f;
        const float* vb = value + (size_t)b * Ss * Hh + h;
        for (int s = len; s < Ss; s++) acc += vb[(size_t)s * Hh];
        g_tail[h * Bb + b] = acc;
    }
}

// ---------------- persistent mega-kernel ----------------
// 128 blocks x 1024 threads. W resident in smem (36 k64-chunks per block).
// LSTM: block = 16 rows (4u x 4g) x 128 b, 4 warpgroups split K. ATTN: block = batch.
__global__ void __launch_bounds__(1024, 1) k_loop(
    const float* __restrict__ emb, const float* __restrict__ fcW,
    const float* __restrict__ fcb, const float* __restrict__ bias1,
    const float* __restrict__ bias2, float* __restrict__ out)
{
    extern __shared__ __align__(16) char dyn[];
    int tid = threadIdx.x;
    int blk = blockIdx.x;
    int r0 = blk * 16;

    // ---- preload W into smem (once) ----
    // chunk c < 20: W1 k-range [c*64, c*64+64); c >= 20: W2 chunk (c-20)
    {
        __half* Wsm = (__half*)dyn;
        for (int i = tid; i < 36 * 16 * 8; i += 1024) {
            int chunk = i >> 7;
            int rem = i & 127;
            int row = rem >> 3, q = rem & 7;
            __half* dst = Wsm + chunk * 1152 + row * 72 + q * 8;
            const __half* src = (chunk < 20)
                ? g_W1h + (size_t)(r0 + row) * K1d + chunk * 64 + q * 8
                : g_W2h + (size_t)(r0 + row) * K2d + (chunk - 20) * 64 + q * 8;
            cp16(dst, src);
        }
        asm volatile("cp.async.commit_group;\ncp.async.wait_group 0;\n");
        __syncthreads();
    }

    // ---- lstm phase ----
    auto lstm_phase = [&](int layer, int slot, const float* bias) {
        const __half* Xa = (layer == 1) ? g_X1h : g_X2h;
        const int split  = (layer == 1) ? 768 : 512;
        const int Kdim   = (layer == 1) ? K1d : K2d;
        const __half* Xb = Xa + (size_t)(split + slot * 512) * Bb;
        float* cst = (layer == 1) ? g_c0 : g_c1;
        const int chunkBase = (layer == 1) ? 0 : 20;

        int u0 = blk * 4;
        int wg = tid >> 8;
        int wt = tid & 255;
        int lane = wt & 31, w8 = wt >> 5;
        int Kwg = Kdim >> 2;
        int wgK0 = wg * Kwg;
        int nst = Kwg >> 6;  // 5 or 4
        char* xb0 = dyn + WB + wg * 2 * XSTG;

        float acc[2][4];
#pragma unroll
        for (int j = 0; j < 2; j++)
#pragma unroll
            for (int q = 0; q < 4; q++) acc[j][q] = 0.f;

        auto issue = [&](int st) {
            int k0 = wgK0 + st * 64;
            __half* sX = (__half*)(xb0 + (st & 1) * XSTG);
            const __half* xbase = (k0 < split) ? (Xa + (size_t)k0 * Bb) : (Xb + (size_t)(k0 - split) * Bb);
#pragma unroll
            for (int it = 0; it < 4; it++) {
                int c = wt + 256 * it;
                int r = c >> 4, q = c & 15;
                cp16(sX + r * 136 + q * 8, xbase + r * Bb + q * 8);
            }
            asm volatile("cp.async.commit_group;\n");
        };

        issue(0);
        for (int st = 0; st < nst; st++) {
            if (st + 1 < nst) {
                issue(st + 1);
                asm volatile("cp.async.wait_group 1;\n");
            } else {
                asm volatile("cp.async.wait_group 0;\n");
            }
            asm volatile("bar.sync %0, 256;" :: "r"(wg + 1) : "memory");

            __half* Wt = (__half*)dyn + (chunkBase + wg * nst + st) * 1152;
            __half* Xs = (__half*)(xb0 + (st & 1) * XSTG);
            unsigned aaddr = (unsigned)__cvta_generic_to_shared(Wt + (lane & 15) * 72 + ((lane >> 4) * 8));
            unsigned bbase = (unsigned)__cvta_generic_to_shared(Xs + (lane & 15) * 136);

#pragma unroll
            for (int ki = 0; ki < 4; ki++) {
                int kc = ki * 16;
                uint32 ah[4];
                asm volatile("ldmatrix.sync.aligned.m8n8.x4.shared.b16 {%0,%1,%2,%3},[%4];"
                             : "=r"(ah[0]), "=r"(ah[1]), "=r"(ah[2]), "=r"(ah[3])
                             : "r"(aaddr + kc * 2));
#pragma unroll
                for (int j = 0; j < 2; j++) {
                    int n0 = w8 * 16 + j * 8;
                    uint32 b0, b1;
                    asm volatile("ldmatrix.sync.aligned.m8n8.x2.trans.shared.b16 {%0,%1},[%2];"
                                 : "=r"(b0), "=r"(b1)
                                 : "r"(bbase + (kc * 136 + n0) * 2));
                    asm volatile("mma.sync.aligned.m16n8k16.row.col.f32.f16.f16.f32 "
                                 "{%0,%1,%2,%3},{%4,%5,%6,%7},{%8,%9},{%0,%1,%2,%3};"
                                 : "+f"(acc[j][0]), "+f"(acc[j][1]), "+f"(acc[j][2]), "+f"(acc[j][3])
                                 : "r"(ah[0]), "r"(ah[1]), "r"(ah[2]), "r"(ah[3]), "r"(b0), "r"(b1));
                }
            }
            asm volatile("bar.sync %0, 256;" :: "r"(wg + 1) : "memory");
        }

        __syncthreads();
        float* P = (float*)(dyn + WB);  // [wg][16][128], aliases X staging
#pragma unroll
        for (int j = 0; j < 2; j++) {
            int n0 = w8 * 16 + j * 8;
            int row = lane >> 2;
            int col = n0 + (lane & 3) * 2;
            *(float2*)(P + wg * 2048 + row * 128 + col)       = make_float2(acc[j][0], acc[j][1]);
            *(float2*)(P + wg * 2048 + (row + 8) * 128 + col) = make_float2(acc[j][2], acc[j][3]);
        }
        __syncthreads();
        if (tid < 512) {
            int b = tid & 127, ul = tid >> 7;
            int u = u0 + ul;
            float gv[4];
#pragma unroll
            for (int g = 0; g < 4; g++) {
                int r = (ul * 4 + g) * 128 + b;
                gv[g] = P[r] + P[2048 + r] + P[4096 + r] + P[6144 + r] + bias[g * Hh + u];
            }
            float c = cst[u * Bb + b];
            float cn = sigf(gv[1]) * c + sigf(gv[0]) * tanhf(gv[2]);
            float h = sigf(gv[3]) * tanhf(cn);
            cst[u * Bb + b] = cn;
            __half hh = __float2half_rn(h);
            if (layer == 1) {
                g_X2h[u * Bb + b] = hh;
                g_X1h[(768 + (slot ^ 1) * 512 + u) * Bb + b] = hh;
            } else {
                g_X2h[(512 + (slot ^ 1) * 512 + u) * Bb + b] = hh;
                g_h1t[b * Hh + u] = h;  // transposed: coalesced attn read
            }
        }
        __syncthreads();
    };

    // ---- attn smem (aliases X staging region) ----
    char* abase = dyn + WB;
    float* sh1  = (float*)abase;             // 2048 B
    half2* sh1h = (half2*)(abase + 2048);    // 512 B
    float* sc   = (float*)(abase + 2560);    // 3200 B
    float* red  = (float*)(abase + 5760);    // 128 B
    float* sb2  = (float*)(abase + 5888);    // 8 B
    float* sctx = (float*)(abase + 6144);    // 32768 B

    for (int t = 0; t < Tt; t++) {
        int slot = t & 1;
        lstm_phase(1, slot, bias1);
        gridbar();
        lstm_phase(2, slot, bias2);
        gridbar();

        // ================= ATTN: block = batch =================
        {
            int b = blk;
            int lane = tid & 31, warp = tid >> 5;

            if (tid < Hh) sh1[tid] = __ldcg(&g_h1t[b * Hh + tid]);
            __syncthreads();
            if (tid < Hh / 2) sh1h[tid] = __floats2half2_rn(sh1[2 * tid], sh1[2 * tid + 1]);
            __syncthreads();

            half2 h1r[2][4];
#pragma unroll
            for (int i = 0; i < 2; i++) {
                const uint4 hv = ((const uint4*)sh1h)[lane + 32 * i];
                h1r[i][0] = *(const half2*)&hv.x; h1r[i][1] = *(const half2*)&hv.y;
                h1r[i][2] = *(const half2*)&hv.z; h1r[i][3] = *(const half2*)&hv.w;
            }

            const uint4* k4 = (const uint4*)(g_kh + (size_t)b * Ss * Hh);
            for (int s = warp; s < Ss; s += 32) {
                const uint4* kr = k4 + (size_t)s * 64;
                float a = 0.0f;
#pragma unroll
                for (int i = 0; i < 2; i++) {
                    uint4 kv = kr[lane + 32 * i];
                    const half2* kp = (const half2*)&kv;
#pragma unroll
                    for (int j = 0; j < 4; j++) {
                        float2 kf = __half22float2(kp[j]);
                        float2 hf = __half22float2(h1r[i][j]);
                        a += kf.x * hf.x + kf.y * hf.y;
                    }
                }
#pragma unroll
                for (int o = 16; o; o >>= 1) a += __shfl_xor_sync(0xffffffffu, a, o);
                if (lane == 0) sc[s] = a;
            }
            __syncthreads();

            float m = (tid < Ss) ? sc[tid] : -3.4e38f;
#pragma unroll
            for (int o = 16; o; o >>= 1) m = fmaxf(m, __shfl_xor_sync(0xffffffffu, m, o));
            if (lane == 0) red[warp] = m;
            __syncthreads();
            if (warp == 0) {
                float v = red[lane];
#pragma unroll
                for (int o = 16; o; o >>= 1) v = fmaxf(v, __shfl_xor_sync(0xffffffffu, v, o));
                if (lane == 0) sb2[0] = v;
            }
            __syncthreads();
            float mx = sb2[0];
            float e = 0.0f;
            if (tid < Ss) { e = expf(sc[tid] - mx); sc[tid] = e; }
            float su = e;
#pragma unroll
            for (int o = 16; o; o >>= 1) su += __shfl_xor_sync(0xffffffffu, su, o);
            __syncthreads();
            if (lane == 0) red[warp] = su;
            __syncthreads();
            if (warp == 0) {
                float v = red[lane];
#pragma unroll
                for (int o = 16; o; o >>= 1) v += __shfl_xor_sync(0xffffffffu, v, o);
                if (lane == 0) sb2[1] = v;
            }
            __syncthreads();
            float rinv = 1.0f / sb2[1];
            int len = g_len[b];

            int c4 = tid & 63, part = tid >> 6;
            const uint4* v4 = (const uint4*)(g_vh + (size_t)b * Ss * Hh);
            float accf[8];
#pragma unroll
            for (int i = 0; i < 8; i++) accf[i] = 0.0f;
            for (int s = part; s < len; s += 16) {
                float ee = sc[s];
                uint4 v = v4[(size_t)s * 64 + c4];
                const half2* vp = (const half2*)&v;
#pragma unroll
                for (int j = 0; j < 4; j++) {
                    float2 vf = __half22float2(vp[j]);
                    accf[2 * j]     += ee * vf.x;
                    accf[2 * j + 1] += ee * vf.y;
                }
            }
            {
                float4* dst = (float4*)(sctx + part * Hh + c4 * 8);
                dst[0] = make_float4(accf[0], accf[1], accf[2], accf[3]);
                dst[1] = make_float4(accf[4], accf[5], accf[6], accf[7]);
            }
            __syncthreads();
            if (tid < Hh) {
                float v = 0.0f;
#pragma unroll
                for (int p = 0; p < 16; p++) v += sctx[p * Hh + tid];
                float ctx = v * rinv + 1e-9f * g_tail[tid * Bb + b];
                g_X1h[tid * Bb + b] = __float2half_rn(ctx);
            }

            const float4* h14 = (const float4*)sh1;
            for (int v = warp; v < Vv; v += 32) {
                const float4* fw = (const float4*)(fcW + v * Hh);
                float a = 0.0f;
#pragma unroll
                for (int i = 0; i < 4; i++) {
                    float4 wv = fw[lane + 32 * i];
                    float4 hv = h14[lane + 32 * i];
                    a += wv.x * hv.x + wv.y * hv.y + wv.z * hv.z + wv.w * hv.w;
                }
#pragma unroll
                for (int o = 16; o; o >>= 1) a += __shfl_xor_sync(0xffffffffu, a, o);
                if (lane == 0) out[(size_t)b * (Tt * Vv) + t * Vv + v] = a + fcb[v];
            }

            if (t < Tt - 1 && tid < Ee) {
                int tok = g_tok[b * Tt + (t + 1)];
                g_X1h[(512 + tid) * Bb + b] = __float2half_rn(emb[tok * Ee + tid]);
            }
        }
        gridbar();
    }
}

// ---------------- host ----------------
extern "C" void kernel_launch(void* const* d_in, const int* in_sizes, int n_in,
                              void* d_out, int out_size) {
    const float* key   = (const float*)d_in[0];
    const float* value = (const float*)d_in[1];
    const void*  dec   = d_in[2];
    const void*  lens  = d_in[3];
    const float* emb   = (const float*)d_in[4];
    const float* Wih1  = (const float*)d_in[5];
    const float* Whh1  = (const float*)d_in[6];
    const float* b1    = (const float*)d_in[7];
    const float* Wih2  = (const float*)d_in[8];
    const float* Whh2  = (const float*)d_in[9];
    const float* b2    = (const float*)d_in[10];
    const float* fcW   = (const float*)d_in[11];
    const float* fcb   = (const float*)d_in[12];
    float* out = (float*)d_out;

    static bool attrSet = false;
    if (!attrSet) {
        cudaFuncSetAttribute(k_loop, cudaFuncAttributeMaxDynamicSharedMemorySize, DYNB);
        attrSet = true;
    }

    k_setup<<<2048, 256>>>(dec, lens, Wih1, Whh1, Wih2, Whh2, key, value, emb);
    k_loop<<<Bb, 1024, DYNB>>>(emb, fcW, fcb, b1, b2, out);
}